// round 6
// baseline (speedup 1.0000x reference)
#include <cuda_runtime.h>
#include <cuda_bf16.h>
#include <cstdint>
#include <cstddef>

#define BB 4
#define TT 4096
#define CC 1024
#define HH 16
#define GG 8
#define HSD 64
#define GTT 512

// ---- scratch (static device globals; no runtime allocation allowed) ----
// grouped, rope'd, split-bf16 q/k/v
__device__ __align__(16) __nv_bfloat16 g_qh[(size_t)BB*HH*GG*GTT*HSD];
__device__ __align__(16) __nv_bfloat16 g_ql[(size_t)BB*HH*GG*GTT*HSD];
__device__ __align__(16) __nv_bfloat16 g_kh[(size_t)BB*HH*GG*GTT*HSD];
__device__ __align__(16) __nv_bfloat16 g_kl[(size_t)BB*HH*GG*GTT*HSD];
__device__ __align__(16) __nv_bfloat16 g_vh[(size_t)BB*HH*GG*GTT*HSD];
__device__ __align__(16) __nv_bfloat16 g_vl[(size_t)BB*HH*GG*GTT*HSD];
// split-bf16 GEMM operands
__device__ __align__(16) __nv_bfloat16 g_xh[(size_t)BB*TT*CC];
__device__ __align__(16) __nv_bfloat16 g_xl[(size_t)BB*TT*CC];
__device__ __align__(16) __nv_bfloat16 g_wqh[(size_t)CC*3*CC];
__device__ __align__(16) __nv_bfloat16 g_wql[(size_t)CC*3*CC];
__device__ __align__(16) __nv_bfloat16 g_woh[(size_t)CC*CC];
__device__ __align__(16) __nv_bfloat16 g_wol[(size_t)CC*CC];
__device__ __align__(16) __nv_bfloat16 g_obh[(size_t)BB*TT*CC];
__device__ __align__(16) __nv_bfloat16 g_obl[(size_t)BB*TT*CC];

// =================== small helpers ===================
__device__ __forceinline__ float hif(float x) {
    return __bfloat162float(__float2bfloat16(x));
}
__device__ __forceinline__ uint32_t packbf(float lo, float hi) {
    uint32_t r;
    asm("cvt.rn.bf16x2.f32 %0,%1,%2;" : "=r"(r) : "f"(hi), "f"(lo));
    return r;
}
__device__ __forceinline__ void cp16(void* s, const void* g) {
    uint32_t sa = (uint32_t)__cvta_generic_to_shared(s);
    asm volatile("cp.async.cg.shared.global [%0], [%1], 16;" :: "r"(sa), "l"(g));
}
__device__ __forceinline__ void cp16s(uint32_t sa, const void* g) {
    asm volatile("cp.async.cg.shared.global [%0], [%1], 16;" :: "r"(sa), "l"(g));
}
__device__ __forceinline__ void ldsm4(uint32_t* r, uint32_t a) {
    asm volatile("ldmatrix.sync.aligned.m8n8.x4.shared.b16 {%0,%1,%2,%3},[%4];"
        : "=r"(r[0]), "=r"(r[1]), "=r"(r[2]), "=r"(r[3]) : "r"(a));
}
__device__ __forceinline__ void ldsm4t(uint32_t* r0, uint32_t* r1, uint32_t a) {
    asm volatile("ldmatrix.sync.aligned.m8n8.x4.trans.shared.b16 {%0,%1,%2,%3},[%4];"
        : "=r"(r0[0]), "=r"(r0[1]), "=r"(r1[0]), "=r"(r1[1]) : "r"(a));
}
__device__ __forceinline__ void ldsm4t4(uint32_t* r, uint32_t a) {
    asm volatile("ldmatrix.sync.aligned.m8n8.x4.trans.shared.b16 {%0,%1,%2,%3},[%4];"
        : "=r"(r[0]), "=r"(r[1]), "=r"(r[2]), "=r"(r[3]) : "r"(a));
}
__device__ __forceinline__ void mma_bf16(float* d, const uint32_t* a,
                                         const uint32_t* b) {
    asm volatile("mma.sync.aligned.m16n8k16.row.col.f32.bf16.bf16.f32 "
        "{%0,%1,%2,%3},{%4,%5,%6,%7},{%8,%9},{%0,%1,%2,%3};"
        : "+f"(d[0]), "+f"(d[1]), "+f"(d[2]), "+f"(d[3])
        : "r"(a[0]), "r"(a[1]), "r"(a[2]), "r"(a[3]), "r"(b[0]), "r"(b[1]));
}
__device__ __forceinline__ uint32_t swz(int r, int c) {
    return (uint32_t)(r * 128 + ((c ^ (r & 7)) << 4));
}
__device__ __forceinline__ void store_split2(
    __nv_bfloat16* hi, __nv_bfloat16* lo, size_t idx, float2 v)
{
    float h0 = hif(v.x), h1 = hif(v.y);
    *(uint32_t*)(hi + idx) = packbf(h0, h1);
    *(uint32_t*)(lo + idx) = packbf(v.x - h0, v.y - h1);
}

// =================== fp32 -> split bf16 (hi + lo) ===================
__global__ __launch_bounds__(256) void split_k(
    const float* __restrict__ in, __nv_bfloat16* __restrict__ hi,
    __nv_bfloat16* __restrict__ lo, int n)
{
    int i = (blockIdx.x * 256 + threadIdx.x) * 4;
    if (i >= n) return;
    float4 v = *(const float4*)(in + i);
    float h0 = hif(v.x), h1 = hif(v.y), h2 = hif(v.z), h3 = hif(v.w);
    *(uint32_t*)(hi + i)     = packbf(h0, h1);
    *(uint32_t*)(hi + i + 2) = packbf(h2, h3);
    *(uint32_t*)(lo + i)     = packbf(v.x - h0, v.y - h1);
    *(uint32_t*)(lo + i + 2) = packbf(v.z - h2, v.w - h3);
}

// =================== split-bf16 3-pass tensor-core GEMM ===================
// FUSE=0: plain fp32 C output.  FUSE=1: RoPE + grouped scatter + split epilogue.
#define SA_PITCH 40
#define SB_PITCH 136
#define AH_OFF 0
#define AL_OFF 5120
#define BH_OFF 10240
#define BL_OFF 14592
#define STG_ELEMS 18944
#define GEMM_SMEM (2 * STG_ELEMS * 2)

__device__ __forceinline__ void prefetch_tiles(
    __nv_bfloat16* smbuf,
    const __nv_bfloat16* Ah, const __nv_bfloat16* Al,
    const __nv_bfloat16* Bh, const __nv_bfloat16* Bl,
    int bm, int bn, int N, int K, int k0, int buf, int tid)
{
    __nv_bfloat16* sb = smbuf + buf * STG_ELEMS;
    #pragma unroll
    for (int c = 0; c < 2; c++) {
        int idx = tid * 8 + c * 2048;
        int ar = idx >> 5, ak = idx & 31;
        cp16(sb + AH_OFF + ar * SA_PITCH + ak,
             Ah + (size_t)(bm + ar) * K + k0 + ak);
        cp16(sb + AL_OFF + ar * SA_PITCH + ak,
             Al + (size_t)(bm + ar) * K + k0 + ak);
        int bk = idx >> 7, bc = idx & 127;
        cp16(sb + BH_OFF + bk * SB_PITCH + bc,
             Bh + (size_t)(k0 + bk) * N + bn + bc);
        cp16(sb + BL_OFF + bk * SB_PITCH + bc,
             Bl + (size_t)(k0 + bk) * N + bn + bc);
    }
    asm volatile("cp.async.commit_group;" ::: "memory");
}

template <int FUSE>
__global__ __launch_bounds__(256) void gemm3_k(
    const __nv_bfloat16* __restrict__ Ah, const __nv_bfloat16* __restrict__ Al,
    const __nv_bfloat16* __restrict__ Bh, const __nv_bfloat16* __restrict__ Bl,
    float* __restrict__ C,
    const float* __restrict__ fcos, const float* __restrict__ fsin,
    int M, int N, int K)
{
    extern __shared__ __nv_bfloat16 smbuf[];
    int tid = threadIdx.x, lane = tid & 31, warp = tid >> 5;
    int bm = blockIdx.y * 128, bn = blockIdx.x * 128;
    int wm = (warp >> 2) * 64, wn = (warp & 3) * 32;
    uint32_t smb = (uint32_t)__cvta_generic_to_shared(smbuf);
    float acc[4][4][4] = {};
    int NK = K >> 5;

    prefetch_tiles(smbuf, Ah, Al, Bh, Bl, bm, bn, N, K, 0, 0, tid);
    for (int kt = 0; kt < NK; kt++) {
        if (kt + 1 < NK) {
            prefetch_tiles(smbuf, Ah, Al, Bh, Bl, bm, bn, N, K,
                           (kt + 1) << 5, (kt + 1) & 1, tid);
            asm volatile("cp.async.wait_group 1;" ::: "memory");
        } else {
            asm volatile("cp.async.wait_group 0;" ::: "memory");
        }
        __syncthreads();
        int sb = (kt & 1) * STG_ELEMS;
        #pragma unroll
        for (int ks = 0; ks < 2; ks++) {
            uint32_t aH[4][4], aL[4][4], bH[4][2], bL[4][2];
            int arow = lane & 15;
            int acb = ks * 32 + ((lane >> 4) << 4);
            #pragma unroll
            for (int mt = 0; mt < 4; mt++) {
                uint32_t ad = smb + (uint32_t)((sb + AH_OFF) * 2
                            + (wm + mt * 16 + arow) * (SA_PITCH * 2) + acb);
                ldsm4(aH[mt], ad);
                ldsm4(aL[mt], ad + (AL_OFF - AH_OFF) * 2);
            }
            int bk = ks * 16 + (lane & 15);
            int bcb = (wn + ((lane >> 4) << 3)) * 2;
            #pragma unroll
            for (int p = 0; p < 2; p++) {
                uint32_t bd = smb + (uint32_t)((sb + BH_OFF) * 2
                            + bk * (SB_PITCH * 2) + bcb + p * 32);
                ldsm4t(bH[2 * p], bH[2 * p + 1], bd);
                ldsm4t(bL[2 * p], bL[2 * p + 1], bd + (BL_OFF - BH_OFF) * 2);
            }
            #pragma unroll
            for (int mt = 0; mt < 4; mt++)
                #pragma unroll
                for (int nt = 0; nt < 4; nt++) {
                    mma_bf16(acc[mt][nt], aH[mt], bH[nt]);
                    mma_bf16(acc[mt][nt], aH[mt], bL[nt]);
                    mma_bf16(acc[mt][nt], aL[mt], bH[nt]);
                }
        }
        __syncthreads();
    }

    if (FUSE == 0) {
        #pragma unroll
        for (int mt = 0; mt < 4; mt++) {
            #pragma unroll
            for (int nt = 0; nt < 4; nt++) {
                int r = bm + wm + mt * 16 + (lane >> 2);
                int c = bn + wn + nt * 8 + ((lane & 3) << 1);
                *(float2*)&C[(size_t)r * N + c] =
                    make_float2(acc[mt][nt][0], acc[mt][nt][1]);
                *(float2*)&C[(size_t)(r + 8) * N + c] =
                    make_float2(acc[mt][nt][2], acc[mt][nt][3]);
            }
        }
    } else {
        // RoPE + grouped scatter + split-bf16 epilogue. Region (q/k/v) is
        // block-uniform: each 128-col tile lies in one 1024-col region.
        int region = bn >> 10;            // 0=q, 1=k, 2=v
        int cbase = (bn & 1023) + wn;
        __nv_bfloat16* dh = (region == 0 ? g_qh : (region == 1 ? g_kh : g_vh));
        __nv_bfloat16* dl = (region == 0 ? g_ql : (region == 1 ? g_kl : g_vl));
        #pragma unroll
        for (int mt = 0; mt < 4; mt++) {
            #pragma unroll
            for (int nt = 0; nt < 4; nt++) {
                int c0 = cbase + nt * 8 + ((lane & 3) << 1);
                int h = c0 >> 6;
                int cj = c0 & 63;
                int j = cj >> 1;
                #pragma unroll
                for (int half = 0; half < 2; half++) {
                    int r = bm + wm + mt * 16 + (lane >> 2) + half * 8;
                    int t = r & (TT - 1), b = r >> 12;
                    float v0 = acc[mt][nt][half * 2];
                    float v1 = acc[mt][nt][half * 2 + 1];
                    if (region < 2) {
                        float cz = fcos[t * 32 + j], sz = fsin[t * 32 + j];
                        float o0 = v0 * cz - v1 * sz;
                        float o1 = v0 * sz + v1 * cz;
                        int h2 = t & 15;
                        int gq = h >> 1;
                        int gtq = ((h & 1) << 8) | (t >> 4);
                        size_t idx = (((size_t)((b * HH + h2) * GG + gq) * GTT
                                     + gtq) * HSD) + cj;
                        store_split2(dh, dl, idx, make_float2(o0, o1));
                    } else {
                        int gv = t >> 9, gtv = t & 511;
                        size_t idx = (((size_t)((b * HH + h) * GG + gv) * GTT
                                     + gtv) * HSD) + cj;
                        store_split2(dh, dl, idx, make_float2(v0, v1));
                    }
                }
            }
        }
    }
}

// =================== tensor-core block-causal flash attention ===================
#define ATT_SMEM 65536

__global__ __launch_bounds__(256) void attn_k() {
    extern __shared__ __align__(16) char smraw[];
    uint32_t smb = (uint32_t)__cvta_generic_to_shared(smraw);
    int tid = threadIdx.x, lane = tid & 31, w = tid >> 5;
    int bx = blockIdx.x;
    int qi = bx & 3;
    int g  = (bx >> 2) & 7;
    int h  = (bx >> 5) & 15;
    int b  = bx >> 9;
    size_t gb = ((size_t)((b * HH + h) * GG + g)) * GTT * HSD;
    const __nv_bfloat16* Qhp = g_qh + gb + (size_t)(128 * qi) * HSD;
    const __nv_bfloat16* Qlp = g_ql + gb + (size_t)(128 * qi) * HSD;
    const __nv_bfloat16* arrp[4] = { g_kh + gb, g_kl + gb, g_vh + gb, g_vl + gb };

    #pragma unroll
    for (int it = 0; it < 8; it++) {
        int cid = tid + it * 256;
        int half = cid >> 10;
        int rc = cid & 1023;
        int r = rc >> 3, c = rc & 7;
        const __nv_bfloat16* src = (half ? Qlp : Qhp) + r * HSD + c * 8;
        cp16s(smb + 32768 + half * 16384 + swz(r, c), src);
    }
    asm volatile("cp.async.commit_group;" ::: "memory");
    asm volatile("cp.async.wait_group 0;" ::: "memory");
    __syncthreads();

    uint32_t qhf[4][4], qlf[4][4];
    int rq = w * 16;
    int sub = lane >> 3;
    #pragma unroll
    for (int kk = 0; kk < 4; kk++) {
        int r = rq + (sub & 1) * 8 + (lane & 7);
        int c = 2 * kk + (sub >> 1);
        uint32_t ad = smb + 32768 + swz(r, c);
        ldsm4(qhf[kk], ad);
        ldsm4(qlf[kk], ad + 16384);
    }
    __syncthreads();

    int ntiles = 2 * qi + 2;

    {
        #pragma unroll
        for (int it = 0; it < 8; it++) {
            int cid = tid + it * 256;
            int arr = cid >> 9;
            int rc = cid & 511;
            int r = rc >> 3, c = rc & 7;
            cp16s(smb + arr * 8192 + swz(r, c),
                  arrp[arr] + (size_t)r * HSD + c * 8);
        }
        asm volatile("cp.async.commit_group;" ::: "memory");
    }

    float oacc[8][4] = {};
    float m_lo = -1e30f, m_hi = -1e30f, l_lo = 0.f, l_hi = 0.f;

    for (int kt = 0; kt < ntiles; kt++) {
        if (kt + 1 < ntiles) {
            int buf = (kt + 1) & 1;
            #pragma unroll
            for (int it = 0; it < 8; it++) {
                int cid = tid + it * 256;
                int arr = cid >> 9;
                int rc = cid & 511;
                int r = rc >> 3, c = rc & 7;
                cp16s(smb + buf * 32768 + arr * 8192 + swz(r, c),
                      arrp[arr] + (size_t)((kt + 1) * 64 + r) * HSD + c * 8);
            }
            asm volatile("cp.async.commit_group;" ::: "memory");
            asm volatile("cp.async.wait_group 1;" ::: "memory");
        } else {
            asm volatile("cp.async.wait_group 0;" ::: "memory");
        }
        __syncthreads();
        uint32_t kb0 = smb + (kt & 1) * 32768;

        float sacc[8][4] = {};
        #pragma unroll
        for (int kk = 0; kk < 4; kk++) {
            #pragma unroll
            for (int tp = 0; tp < 4; tp++) {
                uint32_t kh4[4], kl4[4];
                int r = tp * 16 + (sub >> 1) * 8 + (lane & 7);
                int c = 2 * kk + (sub & 1);
                uint32_t ad = kb0 + swz(r, c);
                ldsm4(kh4, ad);
                ldsm4(kl4, ad + 8192);
                mma_bf16(sacc[2 * tp],     qhf[kk], kh4);
                mma_bf16(sacc[2 * tp],     qhf[kk], kl4);
                mma_bf16(sacc[2 * tp],     qlf[kk], kh4);
                mma_bf16(sacc[2 * tp + 1], qhf[kk], kh4 + 2);
                mma_bf16(sacc[2 * tp + 1], qhf[kk], kl4 + 2);
                mma_bf16(sacc[2 * tp + 1], qlf[kk], kh4 + 2);
            }
        }

        int rowl = 128 * qi + w * 16 + (lane >> 2);
        bool nm = (kt * 64 + 63) > (128 * qi + w * 16);
        #pragma unroll
        for (int t = 0; t < 8; t++) {
            #pragma unroll
            for (int e = 0; e < 4; e++) {
                float s = sacc[t][e] * 0.125f;
                if (nm) {
                    int col = kt * 64 + t * 8 + ((lane & 3) << 1) + (e & 1);
                    int row = rowl + ((e & 2) ? 8 : 0);
                    if (col > row) s = -1e30f;
                }
                sacc[t][e] = s;
            }
        }

        float mlo = -1e30f, mhi = -1e30f;
        #pragma unroll
        for (int t = 0; t < 8; t++) {
            mlo = fmaxf(mlo, fmaxf(sacc[t][0], sacc[t][1]));
            mhi = fmaxf(mhi, fmaxf(sacc[t][2], sacc[t][3]));
        }
        mlo = fmaxf(mlo, __shfl_xor_sync(0xffffffffu, mlo, 1));
        mlo = fmaxf(mlo, __shfl_xor_sync(0xffffffffu, mlo, 2));
        mhi = fmaxf(mhi, __shfl_xor_sync(0xffffffffu, mhi, 1));
        mhi = fmaxf(mhi, __shfl_xor_sync(0xffffffffu, mhi, 2));
        float nmlo = fmaxf(m_lo, mlo), nmhi = fmaxf(m_hi, mhi);
        float clo = __expf(m_lo - nmlo), chi = __expf(m_hi - nmhi);
        m_lo = nmlo; m_hi = nmhi;
        float slo = 0.f, shi = 0.f;
        #pragma unroll
        for (int t = 0; t < 8; t++) {
            float p0 = __expf(sacc[t][0] - nmlo);
            float p1 = __expf(sacc[t][1] - nmlo);
            float p2 = __expf(sacc[t][2] - nmhi);
            float p3 = __expf(sacc[t][3] - nmhi);
            sacc[t][0] = p0; sacc[t][1] = p1; sacc[t][2] = p2; sacc[t][3] = p3;
            slo += p0 + p1; shi += p2 + p3;
        }
        slo += __shfl_xor_sync(0xffffffffu, slo, 1);
        slo += __shfl_xor_sync(0xffffffffu, slo, 2);
        shi += __shfl_xor_sync(0xffffffffu, shi, 1);
        shi += __shfl_xor_sync(0xffffffffu, shi, 2);
        l_lo = l_lo * clo + slo;
        l_hi = l_hi * chi + shi;
        #pragma unroll
        for (int t = 0; t < 8; t++) {
            oacc[t][0] *= clo; oacc[t][1] *= clo;
            oacc[t][2] *= chi; oacc[t][3] *= chi;
        }

        #pragma unroll
        for (int jk = 0; jk < 4; jk++) {
            uint32_t aph[4], apl[4];
            {
                int t0 = 2 * jk, t1 = t0 + 1;
                float h0 = hif(sacc[t0][0]), h1 = hif(sacc[t0][1]);
                float h2 = hif(sacc[t0][2]), h3 = hif(sacc[t0][3]);
                float g0 = hif(sacc[t1][0]), g1 = hif(sacc[t1][1]);
                float g2 = hif(sacc[t1][2]), g3 = hif(sacc[t1][3]);
                aph[0] = packbf(h0, h1); aph[1] = packbf(h2, h3);
                aph[2] = packbf(g0, g1); aph[3] = packbf(g2, g3);
                apl[0] = packbf(sacc[t0][0] - h0, sacc[t0][1] - h1);
                apl[1] = packbf(sacc[t0][2] - h2, sacc[t0][3] - h3);
                apl[2] = packbf(sacc[t1][0] - g0, sacc[t1][1] - g1);
                apl[3] = packbf(sacc[t1][2] - g2, sacc[t1][3] - g3);
            }
            #pragma unroll
            for (int dp = 0; dp < 4; dp++) {
                uint32_t vh4[4], vl4[4];
                int r = jk * 16 + (sub & 1) * 8 + (lane & 7);
                int c = 2 * dp + (sub >> 1);
                uint32_t ad = kb0 + 16384 + swz(r, c);
                ldsm4t4(vh4, ad);
                ldsm4t4(vl4, ad + 8192);
                mma_bf16(oacc[2 * dp],     aph, vh4);
                mma_bf16(oacc[2 * dp],     aph, vl4);
                mma_bf16(oacc[2 * dp],     apl, vh4);
                mma_bf16(oacc[2 * dp + 1], aph, vh4 + 2);
                mma_bf16(oacc[2 * dp + 1], aph, vl4 + 2);
                mma_bf16(oacc[2 * dp + 1], apl, vh4 + 2);
            }
        }
        __syncthreads();
    }

    float ilo = 1.0f / l_lo, ihi = 1.0f / l_hi;
    size_t tau = (size_t)b * TT + g * GTT + 128 * qi + w * 16 + (lane >> 2);
    int colb = h * HSD + ((lane & 3) << 1);
    #pragma unroll
    for (int t = 0; t < 8; t++) {
        float v0 = oacc[t][0] * ilo, v1 = oacc[t][1] * ilo;
        float v2 = oacc[t][2] * ihi, v3 = oacc[t][3] * ihi;
        float h0 = hif(v0), h1 = hif(v1), h2 = hif(v2), h3 = hif(v3);
        size_t o0 = tau * CC + colb + t * 8;
        size_t o1 = (tau + 8) * CC + colb + t * 8;
        *(uint32_t*)(g_obh + o0) = packbf(h0, h1);
        *(uint32_t*)(g_obl + o0) = packbf(v0 - h0, v1 - h1);
        *(uint32_t*)(g_obh + o1) = packbf(h2, h3);
        *(uint32_t*)(g_obl + o1) = packbf(v2 - h2, v3 - h3);
    }
}

// =================== Pooling (qb/kb/vb; L=1 attention is identity) ===================
__global__ __launch_bounds__(64) void pool_k(
    const float* __restrict__ qp, const float* __restrict__ kp,
    const float* __restrict__ vp, float* __restrict__ out)
{
    int bx = blockIdx.x;
    int which = bx / 448;
    int rem = bx - which * 448;
    int g = rem % 7;
    int bh = rem / 7;
    size_t base = ((size_t)bh * GG + g) * GTT * HSD;
    const __nv_bfloat16* sh = (which == 0 ? g_qh : (which == 1 ? g_kh : g_vh)) + base;
    const __nv_bfloat16* sl = (which == 0 ? g_ql : (which == 1 ? g_kl : g_vl)) + base;
    const float* proj = (which == 0 ? qp : (which == 1 ? kp : vp));
    int hs = threadIdx.x;
    float acc = 0.f;
    #pragma unroll 8
    for (int t = 0; t < GTT; t++) {
        float v = __bfloat162float(sh[(size_t)t * HSD + hs])
                + __bfloat162float(sl[(size_t)t * HSD + hs]);
        acc = fmaf(v, proj[t], acc);
    }
    out[(size_t)BB * TT * CC + (size_t)which * (BB * HH * 7 * HSD)
        + (size_t)(bh * 7 + g) * HSD + hs] = acc;
}

// =================== launch ===================
extern "C" void kernel_launch(void* const* d_in, const int* in_sizes, int n_in,
                              void* d_out, int out_size) {
    (void)in_sizes; (void)n_in; (void)out_size;
    const float* x    = (const float*)d_in[0];
    const float* Wqkv = (const float*)d_in[1];
    const float* Wo   = (const float*)d_in[2];
    const float* qp   = (const float*)d_in[3];
    const float* kp   = (const float*)d_in[4];
    const float* vp   = (const float*)d_in[5];
    const float* fc   = (const float*)d_in[6];
    const float* fs   = (const float*)d_in[7];
    float* out = (float*)d_out;

    __nv_bfloat16 *xh, *xl, *wqh, *wql, *woh, *wol, *obh, *obl;
    cudaGetSymbolAddress((void**)&xh, g_xh);
    cudaGetSymbolAddress((void**)&xl, g_xl);
    cudaGetSymbolAddress((void**)&wqh, g_wqh);
    cudaGetSymbolAddress((void**)&wql, g_wql);
    cudaGetSymbolAddress((void**)&woh, g_woh);
    cudaGetSymbolAddress((void**)&wol, g_wol);
    cudaGetSymbolAddress((void**)&obh, g_obh);
    cudaGetSymbolAddress((void**)&obl, g_obl);

    cudaFuncSetAttribute(attn_k, cudaFuncAttributeMaxDynamicSharedMemorySize,
                         ATT_SMEM);
    cudaFuncSetAttribute(gemm3_k<0>, cudaFuncAttributeMaxDynamicSharedMemorySize,
                         GEMM_SMEM);
    cudaFuncSetAttribute(gemm3_k<1>, cudaFuncAttributeMaxDynamicSharedMemorySize,
                         GEMM_SMEM);

    // 0) split inputs to bf16 hi/lo
    int nx = BB * TT * CC;
    split_k<<<(nx / 4 + 255) / 256, 256>>>(x, xh, xl, nx);
    int nwq = CC * 3 * CC;
    split_k<<<(nwq / 4 + 255) / 256, 256>>>(Wqkv, wqh, wql, nwq);
    int nwo = CC * CC;
    split_k<<<(nwo / 4 + 255) / 256, 256>>>(Wo, woh, wol, nwo);

    // 1) qkv = x @ Wqkv with fused RoPE + grouped scatter + split epilogue
    dim3 g1(3 * CC / 128, BB * TT / 128);
    gemm3_k<1><<<g1, 256, GEMM_SMEM>>>(xh, xl, wqh, wql, nullptr, fc, fs,
                                       BB * TT, 3 * CC, CC);
    // 2) tensor-core block-causal attention (emits split-bf16 o)
    attn_k<<<BB * HH * GG * 4, 256, ATT_SMEM>>>();
    // 3) qb/kb/vb pools (tail of d_out)
    pool_k<<<3 * BB * HH * 7, 64>>>(qp, kp, vp, out);
    // 4) out = o @ Wo (head of d_out)
    dim3 g2(CC / 128, BB * TT / 128);
    gemm3_k<0><<<g2, 256, GEMM_SMEM>>>(obh, obl, woh, wol, out, nullptr, nullptr,
                                       BB * TT, CC, CC);
}

// round 7
// speedup vs baseline: 1.4632x; 1.4632x over previous
#include <cuda_runtime.h>
#include <cuda_bf16.h>
#include <cstdint>
#include <cstddef>

#define BB 4
#define TT 4096
#define CC 1024
#define HH 16
#define GG 8
#define HSD 64
#define GTT 512

// ---- scratch (static device globals; no runtime allocation allowed) ----
__device__ __align__(16) float g_qkv[(size_t)BB*TT*3*CC];        // 192 MB
// grouped, rope'd, split-bf16 q/k/v
__device__ __align__(16) __nv_bfloat16 g_qh[(size_t)BB*HH*GG*GTT*HSD];
__device__ __align__(16) __nv_bfloat16 g_ql[(size_t)BB*HH*GG*GTT*HSD];
__device__ __align__(16) __nv_bfloat16 g_kh[(size_t)BB*HH*GG*GTT*HSD];
__device__ __align__(16) __nv_bfloat16 g_kl[(size_t)BB*HH*GG*GTT*HSD];
__device__ __align__(16) __nv_bfloat16 g_vh[(size_t)BB*HH*GG*GTT*HSD];
__device__ __align__(16) __nv_bfloat16 g_vl[(size_t)BB*HH*GG*GTT*HSD];
// split-bf16 GEMM operands
__device__ __align__(16) __nv_bfloat16 g_xh[(size_t)BB*TT*CC];
__device__ __align__(16) __nv_bfloat16 g_xl[(size_t)BB*TT*CC];
__device__ __align__(16) __nv_bfloat16 g_wqh[(size_t)CC*3*CC];
__device__ __align__(16) __nv_bfloat16 g_wql[(size_t)CC*3*CC];
__device__ __align__(16) __nv_bfloat16 g_woh[(size_t)CC*CC];
__device__ __align__(16) __nv_bfloat16 g_wol[(size_t)CC*CC];
__device__ __align__(16) __nv_bfloat16 g_obh[(size_t)BB*TT*CC];
__device__ __align__(16) __nv_bfloat16 g_obl[(size_t)BB*TT*CC];

// =================== small helpers ===================
__device__ __forceinline__ float hif(float x) {
    return __bfloat162float(__float2bfloat16(x));
}
__device__ __forceinline__ uint32_t packbf(float lo, float hi) {
    uint32_t r;
    asm("cvt.rn.bf16x2.f32 %0,%1,%2;" : "=r"(r) : "f"(hi), "f"(lo));
    return r;
}
__device__ __forceinline__ void cp16(void* s, const void* g) {
    uint32_t sa = (uint32_t)__cvta_generic_to_shared(s);
    asm volatile("cp.async.cg.shared.global [%0], [%1], 16;" :: "r"(sa), "l"(g));
}
__device__ __forceinline__ void cp16s(uint32_t sa, const void* g) {
    asm volatile("cp.async.cg.shared.global [%0], [%1], 16;" :: "r"(sa), "l"(g));
}
__device__ __forceinline__ void ldsm4(uint32_t* r, uint32_t a) {
    asm volatile("ldmatrix.sync.aligned.m8n8.x4.shared.b16 {%0,%1,%2,%3},[%4];"
        : "=r"(r[0]), "=r"(r[1]), "=r"(r[2]), "=r"(r[3]) : "r"(a));
}
__device__ __forceinline__ void ldsm4t(uint32_t* r0, uint32_t* r1, uint32_t a) {
    asm volatile("ldmatrix.sync.aligned.m8n8.x4.trans.shared.b16 {%0,%1,%2,%3},[%4];"
        : "=r"(r0[0]), "=r"(r0[1]), "=r"(r1[0]), "=r"(r1[1]) : "r"(a));
}
__device__ __forceinline__ void ldsm4t4(uint32_t* r, uint32_t a) {
    asm volatile("ldmatrix.sync.aligned.m8n8.x4.trans.shared.b16 {%0,%1,%2,%3},[%4];"
        : "=r"(r[0]), "=r"(r[1]), "=r"(r[2]), "=r"(r[3]) : "r"(a));
}
__device__ __forceinline__ void mma_bf16(float* d, const uint32_t* a,
                                         const uint32_t* b) {
    asm volatile("mma.sync.aligned.m16n8k16.row.col.f32.bf16.bf16.f32 "
        "{%0,%1,%2,%3},{%4,%5,%6,%7},{%8,%9},{%0,%1,%2,%3};"
        : "+f"(d[0]), "+f"(d[1]), "+f"(d[2]), "+f"(d[3])
        : "r"(a[0]), "r"(a[1]), "r"(a[2]), "r"(a[3]), "r"(b[0]), "r"(b[1]));
}
__device__ __forceinline__ uint32_t swz(int r, int c) {
    return (uint32_t)(r * 128 + ((c ^ (r & 7)) << 4));
}
__device__ __forceinline__ void store_split2(
    __nv_bfloat16* hi, __nv_bfloat16* lo, size_t idx, float2 v)
{
    float h0 = hif(v.x), h1 = hif(v.y);
    *(uint32_t*)(hi + idx) = packbf(h0, h1);
    *(uint32_t*)(lo + idx) = packbf(v.x - h0, v.y - h1);
}

// =================== fp32 -> split bf16 (hi + lo) ===================
__global__ __launch_bounds__(256) void split_k(
    const float* __restrict__ in, __nv_bfloat16* __restrict__ hi,
    __nv_bfloat16* __restrict__ lo, int n)
{
    int i = (blockIdx.x * 256 + threadIdx.x) * 4;
    if (i >= n) return;
    float4 v = *(const float4*)(in + i);
    float h0 = hif(v.x), h1 = hif(v.y), h2 = hif(v.z), h3 = hif(v.w);
    *(uint32_t*)(hi + i)     = packbf(h0, h1);
    *(uint32_t*)(hi + i + 2) = packbf(h2, h3);
    *(uint32_t*)(lo + i)     = packbf(v.x - h0, v.y - h1);
    *(uint32_t*)(lo + i + 2) = packbf(v.z - h2, v.w - h3);
}

// =================== split-bf16 3-pass tensor-core GEMM ===================
#define SA_PITCH 40
#define SB_PITCH 136
#define AH_OFF 0
#define AL_OFF 5120
#define BH_OFF 10240
#define BL_OFF 14592
#define STG_ELEMS 18944
#define GEMM_SMEM (2 * STG_ELEMS * 2)

__device__ __forceinline__ void prefetch_tiles(
    __nv_bfloat16* smbuf,
    const __nv_bfloat16* Ah, const __nv_bfloat16* Al,
    const __nv_bfloat16* Bh, const __nv_bfloat16* Bl,
    int bm, int bn, int N, int K, int k0, int buf, int tid)
{
    __nv_bfloat16* sb = smbuf + buf * STG_ELEMS;
    #pragma unroll
    for (int c = 0; c < 2; c++) {
        int idx = tid * 8 + c * 2048;
        int ar = idx >> 5, ak = idx & 31;
        cp16(sb + AH_OFF + ar * SA_PITCH + ak,
             Ah + (size_t)(bm + ar) * K + k0 + ak);
        cp16(sb + AL_OFF + ar * SA_PITCH + ak,
             Al + (size_t)(bm + ar) * K + k0 + ak);
        int bk = idx >> 7, bc = idx & 127;
        cp16(sb + BH_OFF + bk * SB_PITCH + bc,
             Bh + (size_t)(k0 + bk) * N + bn + bc);
        cp16(sb + BL_OFF + bk * SB_PITCH + bc,
             Bl + (size_t)(k0 + bk) * N + bn + bc);
    }
    asm volatile("cp.async.commit_group;" ::: "memory");
}

__global__ __launch_bounds__(256) void gemm3_k(
    const __nv_bfloat16* __restrict__ Ah, const __nv_bfloat16* __restrict__ Al,
    const __nv_bfloat16* __restrict__ Bh, const __nv_bfloat16* __restrict__ Bl,
    float* __restrict__ C, int M, int N, int K)
{
    extern __shared__ __nv_bfloat16 smbuf[];
    int tid = threadIdx.x, lane = tid & 31, warp = tid >> 5;
    int bm = blockIdx.y * 128, bn = blockIdx.x * 128;
    int wm = (warp >> 2) * 64, wn = (warp & 3) * 32;
    uint32_t smb = (uint32_t)__cvta_generic_to_shared(smbuf);
    float acc[4][4][4] = {};
    int NK = K >> 5;

    prefetch_tiles(smbuf, Ah, Al, Bh, Bl, bm, bn, N, K, 0, 0, tid);
    for (int kt = 0; kt < NK; kt++) {
        if (kt + 1 < NK) {
            prefetch_tiles(smbuf, Ah, Al, Bh, Bl, bm, bn, N, K,
                           (kt + 1) << 5, (kt + 1) & 1, tid);
            asm volatile("cp.async.wait_group 1;" ::: "memory");
        } else {
            asm volatile("cp.async.wait_group 0;" ::: "memory");
        }
        __syncthreads();
        int sb = (kt & 1) * STG_ELEMS;
        #pragma unroll
        for (int ks = 0; ks < 2; ks++) {
            uint32_t aH[4][4], aL[4][4], bH[4][2], bL[4][2];
            int arow = lane & 15;
            int acb = ks * 32 + ((lane >> 4) << 4);
            #pragma unroll
            for (int mt = 0; mt < 4; mt++) {
                uint32_t ad = smb + (uint32_t)((sb + AH_OFF) * 2
                            + (wm + mt * 16 + arow) * (SA_PITCH * 2) + acb);
                ldsm4(aH[mt], ad);
                ldsm4(aL[mt], ad + (AL_OFF - AH_OFF) * 2);
            }
            int bk = ks * 16 + (lane & 15);
            int bcb = (wn + ((lane >> 4) << 3)) * 2;
            #pragma unroll
            for (int p = 0; p < 2; p++) {
                uint32_t bd = smb + (uint32_t)((sb + BH_OFF) * 2
                            + bk * (SB_PITCH * 2) + bcb + p * 32);
                ldsm4t(bH[2 * p], bH[2 * p + 1], bd);
                ldsm4t(bL[2 * p], bL[2 * p + 1], bd + (BL_OFF - BH_OFF) * 2);
            }
            // pass loop OUTERMOST: 16 independent accumulators between
            // successive writes to the same acc -> HMMA latency hidden.
            #pragma unroll
            for (int pass = 0; pass < 3; pass++) {
                #pragma unroll
                for (int mt = 0; mt < 4; mt++)
                    #pragma unroll
                    for (int nt = 0; nt < 4; nt++)
                        mma_bf16(acc[mt][nt],
                                 (pass == 2) ? aL[mt] : aH[mt],
                                 (pass == 1) ? bL[nt] : bH[nt]);
            }
        }
        __syncthreads();
    }
    #pragma unroll
    for (int mt = 0; mt < 4; mt++) {
        #pragma unroll
        for (int nt = 0; nt < 4; nt++) {
            int r = bm + wm + mt * 16 + (lane >> 2);
            int c = bn + wn + nt * 8 + ((lane & 3) << 1);
            *(float2*)&C[(size_t)r * N + c] =
                make_float2(acc[mt][nt][0], acc[mt][nt][1]);
            *(float2*)&C[(size_t)(r + 8) * N + c] =
                make_float2(acc[mt][nt][2], acc[mt][nt][3]);
        }
    }
}

// =================== RoPE + grouped scatter (emit split bf16) ===================
__global__ __launch_bounds__(256) void rope_k(
    const float* __restrict__ fcos, const float* __restrict__ fsin)
{
    unsigned id = blockIdx.x * 256u + threadIdx.x;
    int j = id & 31;
    int t = (id >> 5) & (TT - 1);
    int h = (id >> 17) & (HH - 1);
    int b = id >> 21;
    const float* row = g_qkv + (size_t)(b * TT + t) * (3 * CC);
    float2 qv = *(const float2*)(row + h * HSD + 2 * j);
    float2 kv = *(const float2*)(row + CC + h * HSD + 2 * j);
    float2 vv = *(const float2*)(row + 2 * CC + h * HSD + 2 * j);
    float c = fcos[t * 32 + j];
    float s = fsin[t * 32 + j];
    float2 qo = make_float2(qv.x * c - qv.y * s, qv.x * s + qv.y * c);
    float2 ko = make_float2(kv.x * c - kv.y * s, kv.x * s + kv.y * c);
    int h2 = t & 15;
    int gq = h >> 1;
    int gtq = ((h & 1) << 8) | (t >> 4);
    size_t qidx = (((size_t)((b * HH + h2) * GG + gq) * GTT + gtq) * HSD) + 2 * j;
    store_split2(g_qh, g_ql, qidx, qo);
    store_split2(g_kh, g_kl, qidx, ko);
    int gv = t >> 9, gtv = t & 511;
    size_t vidx = (((size_t)((b * HH + h) * GG + gv) * GTT + gtv) * HSD) + 2 * j;
    store_split2(g_vh, g_vl, vidx, vv);
}

// =================== tensor-core block-causal flash attention ===================
#define ATT_SMEM 65536

__global__ __launch_bounds__(256) void attn_k() {
    extern __shared__ __align__(16) char smraw[];
    uint32_t smb = (uint32_t)__cvta_generic_to_shared(smraw);
    int tid = threadIdx.x, lane = tid & 31, w = tid >> 5;
    int bx = blockIdx.x;
    int qi = bx & 3;
    int g  = (bx >> 2) & 7;
    int h  = (bx >> 5) & 15;
    int b  = bx >> 9;
    size_t gb = ((size_t)((b * HH + h) * GG + g)) * GTT * HSD;
    const __nv_bfloat16* Qhp = g_qh + gb + (size_t)(128 * qi) * HSD;
    const __nv_bfloat16* Qlp = g_ql + gb + (size_t)(128 * qi) * HSD;
    const __nv_bfloat16* arrp[4] = { g_kh + gb, g_kl + gb, g_vh + gb, g_vl + gb };

    #pragma unroll
    for (int it = 0; it < 8; it++) {
        int cid = tid + it * 256;
        int half = cid >> 10;
        int rc = cid & 1023;
        int r = rc >> 3, c = rc & 7;
        const __nv_bfloat16* src = (half ? Qlp : Qhp) + r * HSD + c * 8;
        cp16s(smb + 32768 + half * 16384 + swz(r, c), src);
    }
    asm volatile("cp.async.commit_group;" ::: "memory");
    asm volatile("cp.async.wait_group 0;" ::: "memory");
    __syncthreads();

    uint32_t qhf[4][4], qlf[4][4];
    int rq = w * 16;
    int sub = lane >> 3;
    #pragma unroll
    for (int kk = 0; kk < 4; kk++) {
        int r = rq + (sub & 1) * 8 + (lane & 7);
        int c = 2 * kk + (sub >> 1);
        uint32_t ad = smb + 32768 + swz(r, c);
        ldsm4(qhf[kk], ad);
        ldsm4(qlf[kk], ad + 16384);
    }
    __syncthreads();

    int ntiles = 2 * qi + 2;

    {
        #pragma unroll
        for (int it = 0; it < 8; it++) {
            int cid = tid + it * 256;
            int arr = cid >> 9;
            int rc = cid & 511;
            int r = rc >> 3, c = rc & 7;
            cp16s(smb + arr * 8192 + swz(r, c),
                  arrp[arr] + (size_t)r * HSD + c * 8);
        }
        asm volatile("cp.async.commit_group;" ::: "memory");
    }

    float oacc[8][4] = {};
    float m_lo = -1e30f, m_hi = -1e30f, l_lo = 0.f, l_hi = 0.f;

    for (int kt = 0; kt < ntiles; kt++) {
        if (kt + 1 < ntiles) {
            int buf = (kt + 1) & 1;
            #pragma unroll
            for (int it = 0; it < 8; it++) {
                int cid = tid + it * 256;
                int arr = cid >> 9;
                int rc = cid & 511;
                int r = rc >> 3, c = rc & 7;
                cp16s(smb + buf * 32768 + arr * 8192 + swz(r, c),
                      arrp[arr] + (size_t)((kt + 1) * 64 + r) * HSD + c * 8);
            }
            asm volatile("cp.async.commit_group;" ::: "memory");
            asm volatile("cp.async.wait_group 1;" ::: "memory");
        } else {
            asm volatile("cp.async.wait_group 0;" ::: "memory");
        }
        __syncthreads();
        uint32_t kb0 = smb + (kt & 1) * 32768;

        float sacc[8][4] = {};
        #pragma unroll
        for (int kk = 0; kk < 4; kk++) {
            #pragma unroll
            for (int tp = 0; tp < 4; tp++) {
                uint32_t kh4[4], kl4[4];
                int r = tp * 16 + (sub >> 1) * 8 + (lane & 7);
                int c = 2 * kk + (sub & 1);
                uint32_t ad = kb0 + swz(r, c);
                ldsm4(kh4, ad);
                ldsm4(kl4, ad + 8192);
                // interleave the two accumulators: ILP 2 within the chain
                mma_bf16(sacc[2 * tp],     qhf[kk], kh4);
                mma_bf16(sacc[2 * tp + 1], qhf[kk], kh4 + 2);
                mma_bf16(sacc[2 * tp],     qhf[kk], kl4);
                mma_bf16(sacc[2 * tp + 1], qhf[kk], kl4 + 2);
                mma_bf16(sacc[2 * tp],     qlf[kk], kh4);
                mma_bf16(sacc[2 * tp + 1], qlf[kk], kh4 + 2);
            }
        }

        int rowl = 128 * qi + w * 16 + (lane >> 2);
        bool nm = (kt * 64 + 63) > (128 * qi + w * 16);
        #pragma unroll
        for (int t = 0; t < 8; t++) {
            #pragma unroll
            for (int e = 0; e < 4; e++) {
                float s = sacc[t][e] * 0.125f;
                if (nm) {
                    int col = kt * 64 + t * 8 + ((lane & 3) << 1) + (e & 1);
                    int row = rowl + ((e & 2) ? 8 : 0);
                    if (col > row) s = -1e30f;
                }
                sacc[t][e] = s;
            }
        }

        float mlo = -1e30f, mhi = -1e30f;
        #pragma unroll
        for (int t = 0; t < 8; t++) {
            mlo = fmaxf(mlo, fmaxf(sacc[t][0], sacc[t][1]));
            mhi = fmaxf(mhi, fmaxf(sacc[t][2], sacc[t][3]));
        }
        mlo = fmaxf(mlo, __shfl_xor_sync(0xffffffffu, mlo, 1));
        mlo = fmaxf(mlo, __shfl_xor_sync(0xffffffffu, mlo, 2));
        mhi = fmaxf(mhi, __shfl_xor_sync(0xffffffffu, mhi, 1));
        mhi = fmaxf(mhi, __shfl_xor_sync(0xffffffffu, mhi, 2));
        float nmlo = fmaxf(m_lo, mlo), nmhi = fmaxf(m_hi, mhi);
        float clo = __expf(m_lo - nmlo), chi = __expf(m_hi - nmhi);
        m_lo = nmlo; m_hi = nmhi;
        float slo = 0.f, shi = 0.f;
        #pragma unroll
        for (int t = 0; t < 8; t++) {
            float p0 = __expf(sacc[t][0] - nmlo);
            float p1 = __expf(sacc[t][1] - nmlo);
            float p2 = __expf(sacc[t][2] - nmhi);
            float p3 = __expf(sacc[t][3] - nmhi);
            sacc[t][0] = p0; sacc[t][1] = p1; sacc[t][2] = p2; sacc[t][3] = p3;
            slo += p0 + p1; shi += p2 + p3;
        }
        slo += __shfl_xor_sync(0xffffffffu, slo, 1);
        slo += __shfl_xor_sync(0xffffffffu, slo, 2);
        shi += __shfl_xor_sync(0xffffffffu, shi, 1);
        shi += __shfl_xor_sync(0xffffffffu, shi, 2);
        l_lo = l_lo * clo + slo;
        l_hi = l_hi * chi + shi;
        #pragma unroll
        for (int t = 0; t < 8; t++) {
            oacc[t][0] *= clo; oacc[t][1] *= clo;
            oacc[t][2] *= chi; oacc[t][3] *= chi;
        }

        #pragma unroll
        for (int jk = 0; jk < 4; jk++) {
            uint32_t aph[4], apl[4];
            {
                int t0 = 2 * jk, t1 = t0 + 1;
                float h0 = hif(sacc[t0][0]), h1 = hif(sacc[t0][1]);
                float h2 = hif(sacc[t0][2]), h3 = hif(sacc[t0][3]);
                float g0 = hif(sacc[t1][0]), g1 = hif(sacc[t1][1]);
                float g2 = hif(sacc[t1][2]), g3 = hif(sacc[t1][3]);
                aph[0] = packbf(h0, h1); aph[1] = packbf(h2, h3);
                aph[2] = packbf(g0, g1); aph[3] = packbf(g2, g3);
                apl[0] = packbf(sacc[t0][0] - h0, sacc[t0][1] - h1);
                apl[1] = packbf(sacc[t0][2] - h2, sacc[t0][3] - h3);
                apl[2] = packbf(sacc[t1][0] - g0, sacc[t1][1] - g1);
                apl[3] = packbf(sacc[t1][2] - g2, sacc[t1][3] - g3);
            }
            #pragma unroll
            for (int dp = 0; dp < 4; dp++) {
                uint32_t vh4[4], vl4[4];
                int r = jk * 16 + (sub & 1) * 8 + (lane & 7);
                int c = 2 * dp + (sub >> 1);
                uint32_t ad = kb0 + 16384 + swz(r, c);
                ldsm4t4(vh4, ad);
                ldsm4t4(vl4, ad + 8192);
                mma_bf16(oacc[2 * dp],     aph, vh4);
                mma_bf16(oacc[2 * dp + 1], aph, vh4 + 2);
                mma_bf16(oacc[2 * dp],     aph, vl4);
                mma_bf16(oacc[2 * dp + 1], aph, vl4 + 2);
                mma_bf16(oacc[2 * dp],     apl, vh4);
                mma_bf16(oacc[2 * dp + 1], apl, vh4 + 2);
            }
        }
        __syncthreads();
    }

    float ilo = 1.0f / l_lo, ihi = 1.0f / l_hi;
    size_t tau = (size_t)b * TT + g * GTT + 128 * qi + w * 16 + (lane >> 2);
    int colb = h * HSD + ((lane & 3) << 1);
    #pragma unroll
    for (int t = 0; t < 8; t++) {
        float v0 = oacc[t][0] * ilo, v1 = oacc[t][1] * ilo;
        float v2 = oacc[t][2] * ihi, v3 = oacc[t][3] * ihi;
        float h0 = hif(v0), h1 = hif(v1), h2 = hif(v2), h3 = hif(v3);
        size_t o0 = tau * CC + colb + t * 8;
        size_t o1 = (tau + 8) * CC + colb + t * 8;
        *(uint32_t*)(g_obh + o0) = packbf(h0, h1);
        *(uint32_t*)(g_obl + o0) = packbf(v0 - h0, v1 - h1);
        *(uint32_t*)(g_obh + o1) = packbf(h2, h3);
        *(uint32_t*)(g_obl + o1) = packbf(v2 - h2, v3 - h3);
    }
}

// =================== Pooling (qb/kb/vb; L=1 attention is identity) ===================
__global__ __launch_bounds__(64) void pool_k(
    const float* __restrict__ qp, const float* __restrict__ kp,
    const float* __restrict__ vp, float* __restrict__ out)
{
    int bx = blockIdx.x;
    int which = bx / 448;
    int rem = bx - which * 448;
    int g = rem % 7;
    int bh = rem / 7;
    size_t base = ((size_t)bh * GG + g) * GTT * HSD;
    const __nv_bfloat16* sh = (which == 0 ? g_qh : (which == 1 ? g_kh : g_vh)) + base;
    const __nv_bfloat16* sl = (which == 0 ? g_ql : (which == 1 ? g_kl : g_vl)) + base;
    const float* proj = (which == 0 ? qp : (which == 1 ? kp : vp));
    int hs = threadIdx.x;
    float acc = 0.f;
    #pragma unroll 8
    for (int t = 0; t < GTT; t++) {
        float v = __bfloat162float(sh[(size_t)t * HSD + hs])
                + __bfloat162float(sl[(size_t)t * HSD + hs]);
        acc = fmaf(v, proj[t], acc);
    }
    out[(size_t)BB * TT * CC + (size_t)which * (BB * HH * 7 * HSD)
        + (size_t)(bh * 7 + g) * HSD + hs] = acc;
}

// =================== launch ===================
extern "C" void kernel_launch(void* const* d_in, const int* in_sizes, int n_in,
                              void* d_out, int out_size) {
    (void)in_sizes; (void)n_in; (void)out_size;
    const float* x    = (const float*)d_in[0];
    const float* Wqkv = (const float*)d_in[1];
    const float* Wo   = (const float*)d_in[2];
    const float* qp   = (const float*)d_in[3];
    const float* kp   = (const float*)d_in[4];
    const float* vp   = (const float*)d_in[5];
    const float* fc   = (const float*)d_in[6];
    const float* fs   = (const float*)d_in[7];
    float* out = (float*)d_out;

    float* qkv_p;
    __nv_bfloat16 *xh, *xl, *wqh, *wql, *woh, *wol, *obh, *obl;
    cudaGetSymbolAddress((void**)&qkv_p, g_qkv);
    cudaGetSymbolAddress((void**)&xh, g_xh);
    cudaGetSymbolAddress((void**)&xl, g_xl);
    cudaGetSymbolAddress((void**)&wqh, g_wqh);
    cudaGetSymbolAddress((void**)&wql, g_wql);
    cudaGetSymbolAddress((void**)&woh, g_woh);
    cudaGetSymbolAddress((void**)&wol, g_wol);
    cudaGetSymbolAddress((void**)&obh, g_obh);
    cudaGetSymbolAddress((void**)&obl, g_obl);

    cudaFuncSetAttribute(attn_k, cudaFuncAttributeMaxDynamicSharedMemorySize,
                         ATT_SMEM);
    cudaFuncSetAttribute(gemm3_k, cudaFuncAttributeMaxDynamicSharedMemorySize,
                         GEMM_SMEM);

    // 0) split inputs to bf16 hi/lo
    int nx = BB * TT * CC;
    split_k<<<(nx / 4 + 255) / 256, 256>>>(x, xh, xl, nx);
    int nwq = CC * 3 * CC;
    split_k<<<(nwq / 4 + 255) / 256, 256>>>(Wqkv, wqh, wql, nwq);
    int nwo = CC * CC;
    split_k<<<(nwo / 4 + 255) / 256, 256>>>(Wo, woh, wol, nwo);

    // 1) qkv = x @ Wqkv  (tensor cores)
    dim3 g1(3 * CC / 128, BB * TT / 128);
    gemm3_k<<<g1, 256, GEMM_SMEM>>>(xh, xl, wqh, wql, qkv_p,
                                    BB * TT, 3 * CC, CC);
    // 2) rope + grouped scatter (split bf16)
    rope_k<<<(BB * HH * TT * 32) / 256, 256>>>(fc, fs);
    // 3) tensor-core block-causal attention (emits split-bf16 o)
    attn_k<<<BB * HH * GG * 4, 256, ATT_SMEM>>>();
    // 4) qb/kb/vb pools (tail of d_out)
    pool_k<<<3 * BB * HH * 7, 64>>>(qp, kp, vp, out);
    // 5) out = o @ Wo (head of d_out)
    dim3 g2(CC / 128, BB * TT / 128);
    gemm3_k<<<g2, 256, GEMM_SMEM>>>(obh, obl, woh, wol, out,
                                    BB * TT, CC, CC);
}

// round 8
// speedup vs baseline: 1.4954x; 1.0220x over previous
#include <cuda_runtime.h>
#include <cuda_bf16.h>
#include <cstdint>
#include <cstddef>

#define BB 4
#define TT 4096
#define CC 1024
#define HH 16
#define GG 8
#define HSD 64
#define GTT 512

// ---- scratch (static device globals; no runtime allocation allowed) ----
__device__ __align__(16) float g_qkv[(size_t)BB*TT*3*CC];        // 192 MB
__device__ __align__(16) __nv_bfloat16 g_qh[(size_t)BB*HH*GG*GTT*HSD];
__device__ __align__(16) __nv_bfloat16 g_ql[(size_t)BB*HH*GG*GTT*HSD];
__device__ __align__(16) __nv_bfloat16 g_kh[(size_t)BB*HH*GG*GTT*HSD];
__device__ __align__(16) __nv_bfloat16 g_kl[(size_t)BB*HH*GG*GTT*HSD];
__device__ __align__(16) __nv_bfloat16 g_vh[(size_t)BB*HH*GG*GTT*HSD];
__device__ __align__(16) __nv_bfloat16 g_vl[(size_t)BB*HH*GG*GTT*HSD];
__device__ __align__(16) __nv_bfloat16 g_xh[(size_t)BB*TT*CC];
__device__ __align__(16) __nv_bfloat16 g_xl[(size_t)BB*TT*CC];
__device__ __align__(16) __nv_bfloat16 g_wqh[(size_t)CC*3*CC];
__device__ __align__(16) __nv_bfloat16 g_wql[(size_t)CC*3*CC];
__device__ __align__(16) __nv_bfloat16 g_woh[(size_t)CC*CC];
__device__ __align__(16) __nv_bfloat16 g_wol[(size_t)CC*CC];
__device__ __align__(16) __nv_bfloat16 g_obh[(size_t)BB*TT*CC];
__device__ __align__(16) __nv_bfloat16 g_obl[(size_t)BB*TT*CC];

// =================== small helpers ===================
__device__ __forceinline__ float hif(float x) {
    return __bfloat162float(__float2bfloat16(x));
}
__device__ __forceinline__ uint32_t packbf(float lo, float hi) {
    uint32_t r;
    asm("cvt.rn.bf16x2.f32 %0,%1,%2;" : "=r"(r) : "f"(hi), "f"(lo));
    return r;
}
__device__ __forceinline__ void cp16(void* s, const void* g) {
    uint32_t sa = (uint32_t)__cvta_generic_to_shared(s);
    asm volatile("cp.async.cg.shared.global [%0], [%1], 16;" :: "r"(sa), "l"(g));
}
__device__ __forceinline__ void cp16s(uint32_t sa, const void* g) {
    asm volatile("cp.async.cg.shared.global [%0], [%1], 16;" :: "r"(sa), "l"(g));
}
__device__ __forceinline__ void ldsm4(uint32_t* r, uint32_t a) {
    asm volatile("ldmatrix.sync.aligned.m8n8.x4.shared.b16 {%0,%1,%2,%3},[%4];"
        : "=r"(r[0]), "=r"(r[1]), "=r"(r[2]), "=r"(r[3]) : "r"(a));
}
__device__ __forceinline__ void ldsm4t(uint32_t* r0, uint32_t* r1, uint32_t a) {
    asm volatile("ldmatrix.sync.aligned.m8n8.x4.trans.shared.b16 {%0,%1,%2,%3},[%4];"
        : "=r"(r0[0]), "=r"(r0[1]), "=r"(r1[0]), "=r"(r1[1]) : "r"(a));
}
__device__ __forceinline__ void ldsm4t4(uint32_t* r, uint32_t a) {
    asm volatile("ldmatrix.sync.aligned.m8n8.x4.trans.shared.b16 {%0,%1,%2,%3},[%4];"
        : "=r"(r[0]), "=r"(r[1]), "=r"(r[2]), "=r"(r[3]) : "r"(a));
}
__device__ __forceinline__ void mma_bf16(float* d, const uint32_t* a,
                                         const uint32_t* b) {
    asm volatile("mma.sync.aligned.m16n8k16.row.col.f32.bf16.bf16.f32 "
        "{%0,%1,%2,%3},{%4,%5,%6,%7},{%8,%9},{%0,%1,%2,%3};"
        : "+f"(d[0]), "+f"(d[1]), "+f"(d[2]), "+f"(d[3])
        : "r"(a[0]), "r"(a[1]), "r"(a[2]), "r"(a[3]), "r"(b[0]), "r"(b[1]));
}
__device__ __forceinline__ uint32_t swz(int r, int c) {
    return (uint32_t)(r * 128 + ((c ^ (r & 7)) << 4));
}
__device__ __forceinline__ void store_split2(
    __nv_bfloat16* hi, __nv_bfloat16* lo, size_t idx, float2 v)
{
    float h0 = hif(v.x), h1 = hif(v.y);
    *(uint32_t*)(hi + idx) = packbf(h0, h1);
    *(uint32_t*)(lo + idx) = packbf(v.x - h0, v.y - h1);
}

// =================== fp32 -> split bf16 (hi + lo) ===================
__global__ __launch_bounds__(256) void split_k(
    const float* __restrict__ in, __nv_bfloat16* __restrict__ hi,
    __nv_bfloat16* __restrict__ lo, int n)
{
    int i = (blockIdx.x * 256 + threadIdx.x) * 4;
    if (i >= n) return;
    float4 v = *(const float4*)(in + i);
    float h0 = hif(v.x), h1 = hif(v.y), h2 = hif(v.z), h3 = hif(v.w);
    *(uint32_t*)(hi + i)     = packbf(h0, h1);
    *(uint32_t*)(hi + i + 2) = packbf(h2, h3);
    *(uint32_t*)(lo + i)     = packbf(v.x - h0, v.y - h1);
    *(uint32_t*)(lo + i + 2) = packbf(v.z - h2, v.w - h3);
}

// =================== split-bf16 3-pass tensor-core GEMM ===================
// 3-stage cp.async pipeline, ONE __syncthreads per k-tile.
#define SA_PITCH 40
#define SB_PITCH 136
#define AH_OFF 0
#define AL_OFF 5120
#define BH_OFF 10240
#define BL_OFF 14592
#define STG_ELEMS 18944
#define GEMM_SMEM (3 * STG_ELEMS * 2)

__device__ __forceinline__ void prefetch_tiles(
    __nv_bfloat16* smbuf,
    const __nv_bfloat16* Ah, const __nv_bfloat16* Al,
    const __nv_bfloat16* Bh, const __nv_bfloat16* Bl,
    int bm, int bn, int N, int K, int k0, int buf, int tid)
{
    __nv_bfloat16* sb = smbuf + buf * STG_ELEMS;
    #pragma unroll
    for (int c = 0; c < 2; c++) {
        int idx = tid * 8 + c * 2048;
        int ar = idx >> 5, ak = idx & 31;
        cp16(sb + AH_OFF + ar * SA_PITCH + ak,
             Ah + (size_t)(bm + ar) * K + k0 + ak);
        cp16(sb + AL_OFF + ar * SA_PITCH + ak,
             Al + (size_t)(bm + ar) * K + k0 + ak);
        int bk = idx >> 7, bc = idx & 127;
        cp16(sb + BH_OFF + bk * SB_PITCH + bc,
             Bh + (size_t)(k0 + bk) * N + bn + bc);
        cp16(sb + BL_OFF + bk * SB_PITCH + bc,
             Bl + (size_t)(k0 + bk) * N + bn + bc);
    }
    asm volatile("cp.async.commit_group;" ::: "memory");
}

__global__ __launch_bounds__(256) void gemm3_k(
    const __nv_bfloat16* __restrict__ Ah, const __nv_bfloat16* __restrict__ Al,
    const __nv_bfloat16* __restrict__ Bh, const __nv_bfloat16* __restrict__ Bl,
    float* __restrict__ C, int M, int N, int K)
{
    extern __shared__ __nv_bfloat16 smbuf[];
    int tid = threadIdx.x, lane = tid & 31, warp = tid >> 5;
    int bm = blockIdx.y * 128, bn = blockIdx.x * 128;
    int wm = (warp >> 2) * 64, wn = (warp & 3) * 32;
    uint32_t smb = (uint32_t)__cvta_generic_to_shared(smbuf);
    float acc[4][4][4] = {};
    int NK = K >> 5;

    prefetch_tiles(smbuf, Ah, Al, Bh, Bl, bm, bn, N, K, 0, 0, tid);
    if (NK > 1)
        prefetch_tiles(smbuf, Ah, Al, Bh, Bl, bm, bn, N, K, 32, 1, tid);

    int scur = 0;   // stage being consumed
    int snx2 = 2;   // stage to prefetch into (kt+2)
    for (int kt = 0; kt < NK; kt++) {
        if (kt + 1 < NK)
            asm volatile("cp.async.wait_group 1;" ::: "memory");
        else
            asm volatile("cp.async.wait_group 0;" ::: "memory");
        __syncthreads();
        // prefetch kt+2 into the stage all warps just finished (kt-1's buffer)
        if (kt + 2 < NK)
            prefetch_tiles(smbuf, Ah, Al, Bh, Bl, bm, bn, N, K,
                           (kt + 2) << 5, snx2, tid);
        int sb = scur * STG_ELEMS;
        #pragma unroll
        for (int ks = 0; ks < 2; ks++) {
            uint32_t aH[4][4], aL[4][4], bH[4][2], bL[4][2];
            int arow = lane & 15;
            int acb = ks * 32 + ((lane >> 4) << 4);
            #pragma unroll
            for (int mt = 0; mt < 4; mt++) {
                uint32_t ad = smb + (uint32_t)((sb + AH_OFF) * 2
                            + (wm + mt * 16 + arow) * (SA_PITCH * 2) + acb);
                ldsm4(aH[mt], ad);
                ldsm4(aL[mt], ad + (AL_OFF - AH_OFF) * 2);
            }
            int bk = ks * 16 + (lane & 15);
            int bcb = (wn + ((lane >> 4) << 3)) * 2;
            #pragma unroll
            for (int p = 0; p < 2; p++) {
                uint32_t bd = smb + (uint32_t)((sb + BH_OFF) * 2
                            + bk * (SB_PITCH * 2) + bcb + p * 32);
                ldsm4t(bH[2 * p], bH[2 * p + 1], bd);
                ldsm4t(bL[2 * p], bL[2 * p + 1], bd + (BL_OFF - BH_OFF) * 2);
            }
            #pragma unroll
            for (int pass = 0; pass < 3; pass++) {
                #pragma unroll
                for (int mt = 0; mt < 4; mt++)
                    #pragma unroll
                    for (int nt = 0; nt < 4; nt++)
                        mma_bf16(acc[mt][nt],
                                 (pass == 2) ? aL[mt] : aH[mt],
                                 (pass == 1) ? bL[nt] : bH[nt]);
            }
        }
        scur = (scur == 2) ? 0 : scur + 1;
        snx2 = (snx2 == 2) ? 0 : snx2 + 1;
    }
    #pragma unroll
    for (int mt = 0; mt < 4; mt++) {
        #pragma unroll
        for (int nt = 0; nt < 4; nt++) {
            int r = bm + wm + mt * 16 + (lane >> 2);
            int c = bn + wn + nt * 8 + ((lane & 3) << 1);
            *(float2*)&C[(size_t)r * N + c] =
                make_float2(acc[mt][nt][0], acc[mt][nt][1]);
            *(float2*)&C[(size_t)(r + 8) * N + c] =
                make_float2(acc[mt][nt][2], acc[mt][nt][3]);
        }
    }
}

// =================== RoPE + grouped scatter (emit split bf16) ===================
__global__ __launch_bounds__(256) void rope_k(
    const float* __restrict__ fcos, const float* __restrict__ fsin)
{
    unsigned id = blockIdx.x * 256u + threadIdx.x;
    int j = id & 31;
    int t = (id >> 5) & (TT - 1);
    int h = (id >> 17) & (HH - 1);
    int b = id >> 21;
    const float* row = g_qkv + (size_t)(b * TT + t) * (3 * CC);
    float2 qv = *(const float2*)(row + h * HSD + 2 * j);
    float2 kv = *(const float2*)(row + CC + h * HSD + 2 * j);
    float2 vv = *(const float2*)(row + 2 * CC + h * HSD + 2 * j);
    float c = fcos[t * 32 + j];
    float s = fsin[t * 32 + j];
    float2 qo = make_float2(qv.x * c - qv.y * s, qv.x * s + qv.y * c);
    float2 ko = make_float2(kv.x * c - kv.y * s, kv.x * s + kv.y * c);
    int h2 = t & 15;
    int gq = h >> 1;
    int gtq = ((h & 1) << 8) | (t >> 4);
    size_t qidx = (((size_t)((b * HH + h2) * GG + gq) * GTT + gtq) * HSD) + 2 * j;
    store_split2(g_qh, g_ql, qidx, qo);
    store_split2(g_kh, g_kl, qidx, ko);
    int gv = t >> 9, gtv = t & 511;
    size_t vidx = (((size_t)((b * HH + h) * GG + gv) * GTT + gtv) * HSD) + 2 * j;
    store_split2(g_vh, g_vl, vidx, vv);
}

// =================== tensor-core block-causal flash attention ===================
#define ATT_SMEM 65536

__global__ __launch_bounds__(256) void attn_k() {
    extern __shared__ __align__(16) char smraw[];
    uint32_t smb = (uint32_t)__cvta_generic_to_shared(smraw);
    int tid = threadIdx.x, lane = tid & 31, w = tid >> 5;
    int bx = blockIdx.x;
    int qi = bx & 3;
    int g  = (bx >> 2) & 7;
    int h  = (bx >> 5) & 15;
    int b  = bx >> 9;
    size_t gb = ((size_t)((b * HH + h) * GG + g)) * GTT * HSD;
    const __nv_bfloat16* Qhp = g_qh + gb + (size_t)(128 * qi) * HSD;
    const __nv_bfloat16* Qlp = g_ql + gb + (size_t)(128 * qi) * HSD;
    const __nv_bfloat16* arrp[4] = { g_kh + gb, g_kl + gb, g_vh + gb, g_vl + gb };

    #pragma unroll
    for (int it = 0; it < 8; it++) {
        int cid = tid + it * 256;
        int half = cid >> 10;
        int rc = cid & 1023;
        int r = rc >> 3, c = rc & 7;
        const __nv_bfloat16* src = (half ? Qlp : Qhp) + r * HSD + c * 8;
        cp16s(smb + 32768 + half * 16384 + swz(r, c), src);
    }
    asm volatile("cp.async.commit_group;" ::: "memory");
    asm volatile("cp.async.wait_group 0;" ::: "memory");
    __syncthreads();

    uint32_t qhf[4][4], qlf[4][4];
    int rq = w * 16;
    int sub = lane >> 3;
    #pragma unroll
    for (int kk = 0; kk < 4; kk++) {
        int r = rq + (sub & 1) * 8 + (lane & 7);
        int c = 2 * kk + (sub >> 1);
        uint32_t ad = smb + 32768 + swz(r, c);
        ldsm4(qhf[kk], ad);
        ldsm4(qlf[kk], ad + 16384);
    }
    __syncthreads();

    int ntiles = 2 * qi + 2;

    {
        #pragma unroll
        for (int it = 0; it < 8; it++) {
            int cid = tid + it * 256;
            int arr = cid >> 9;
            int rc = cid & 511;
            int r = rc >> 3, c = rc & 7;
            cp16s(smb + arr * 8192 + swz(r, c),
                  arrp[arr] + (size_t)r * HSD + c * 8);
        }
        asm volatile("cp.async.commit_group;" ::: "memory");
    }

    float oacc[8][4] = {};
    float m_lo = -1e30f, m_hi = -1e30f, l_lo = 0.f, l_hi = 0.f;

    for (int kt = 0; kt < ntiles; kt++) {
        if (kt + 1 < ntiles) {
            int buf = (kt + 1) & 1;
            #pragma unroll
            for (int it = 0; it < 8; it++) {
                int cid = tid + it * 256;
                int arr = cid >> 9;
                int rc = cid & 511;
                int r = rc >> 3, c = rc & 7;
                cp16s(smb + buf * 32768 + arr * 8192 + swz(r, c),
                      arrp[arr] + (size_t)((kt + 1) * 64 + r) * HSD + c * 8);
            }
            asm volatile("cp.async.commit_group;" ::: "memory");
            asm volatile("cp.async.wait_group 1;" ::: "memory");
        } else {
            asm volatile("cp.async.wait_group 0;" ::: "memory");
        }
        __syncthreads();
        uint32_t kb0 = smb + (kt & 1) * 32768;

        float sacc[8][4] = {};
        #pragma unroll
        for (int kk = 0; kk < 4; kk++) {
            #pragma unroll
            for (int tp = 0; tp < 4; tp++) {
                uint32_t kh4[4], kl4[4];
                int r = tp * 16 + (sub >> 1) * 8 + (lane & 7);
                int c = 2 * kk + (sub & 1);
                uint32_t ad = kb0 + swz(r, c);
                ldsm4(kh4, ad);
                ldsm4(kl4, ad + 8192);
                mma_bf16(sacc[2 * tp],     qhf[kk], kh4);
                mma_bf16(sacc[2 * tp + 1], qhf[kk], kh4 + 2);
                mma_bf16(sacc[2 * tp],     qhf[kk], kl4);
                mma_bf16(sacc[2 * tp + 1], qhf[kk], kl4 + 2);
                mma_bf16(sacc[2 * tp],     qlf[kk], kh4);
                mma_bf16(sacc[2 * tp + 1], qlf[kk], kh4 + 2);
            }
        }

        int rowl = 128 * qi + w * 16 + (lane >> 2);
        bool nm = (kt * 64 + 63) > (128 * qi + w * 16);
        #pragma unroll
        for (int t = 0; t < 8; t++) {
            #pragma unroll
            for (int e = 0; e < 4; e++) {
                float s = sacc[t][e] * 0.125f;
                if (nm) {
                    int col = kt * 64 + t * 8 + ((lane & 3) << 1) + (e & 1);
                    int row = rowl + ((e & 2) ? 8 : 0);
                    if (col > row) s = -1e30f;
                }
                sacc[t][e] = s;
            }
        }

        float mlo = -1e30f, mhi = -1e30f;
        #pragma unroll
        for (int t = 0; t < 8; t++) {
            mlo = fmaxf(mlo, fmaxf(sacc[t][0], sacc[t][1]));
            mhi = fmaxf(mhi, fmaxf(sacc[t][2], sacc[t][3]));
        }
        mlo = fmaxf(mlo, __shfl_xor_sync(0xffffffffu, mlo, 1));
        mlo = fmaxf(mlo, __shfl_xor_sync(0xffffffffu, mlo, 2));
        mhi = fmaxf(mhi, __shfl_xor_sync(0xffffffffu, mhi, 1));
        mhi = fmaxf(mhi, __shfl_xor_sync(0xffffffffu, mhi, 2));
        float nmlo = fmaxf(m_lo, mlo), nmhi = fmaxf(m_hi, mhi);
        float clo = __expf(m_lo - nmlo), chi = __expf(m_hi - nmhi);
        m_lo = nmlo; m_hi = nmhi;
        float slo = 0.f, shi = 0.f;
        #pragma unroll
        for (int t = 0; t < 8; t++) {
            float p0 = __expf(sacc[t][0] - nmlo);
            float p1 = __expf(sacc[t][1] - nmlo);
            float p2 = __expf(sacc[t][2] - nmhi);
            float p3 = __expf(sacc[t][3] - nmhi);
            sacc[t][0] = p0; sacc[t][1] = p1; sacc[t][2] = p2; sacc[t][3] = p3;
            slo += p0 + p1; shi += p2 + p3;
        }
        slo += __shfl_xor_sync(0xffffffffu, slo, 1);
        slo += __shfl_xor_sync(0xffffffffu, slo, 2);
        shi += __shfl_xor_sync(0xffffffffu, shi, 1);
        shi += __shfl_xor_sync(0xffffffffu, shi, 2);
        l_lo = l_lo * clo + slo;
        l_hi = l_hi * chi + shi;
        #pragma unroll
        for (int t = 0; t < 8; t++) {
            oacc[t][0] *= clo; oacc[t][1] *= clo;
            oacc[t][2] *= chi; oacc[t][3] *= chi;
        }

        #pragma unroll
        for (int jk = 0; jk < 4; jk++) {
            uint32_t aph[4], apl[4];
            {
                int t0 = 2 * jk, t1 = t0 + 1;
                float h0 = hif(sacc[t0][0]), h1 = hif(sacc[t0][1]);
                float h2 = hif(sacc[t0][2]), h3 = hif(sacc[t0][3]);
                float g0 = hif(sacc[t1][0]), g1 = hif(sacc[t1][1]);
                float g2 = hif(sacc[t1][2]), g3 = hif(sacc[t1][3]);
                aph[0] = packbf(h0, h1); aph[1] = packbf(h2, h3);
                aph[2] = packbf(g0, g1); aph[3] = packbf(g2, g3);
                apl[0] = packbf(sacc[t0][0] - h0, sacc[t0][1] - h1);
                apl[1] = packbf(sacc[t0][2] - h2, sacc[t0][3] - h3);
                apl[2] = packbf(sacc[t1][0] - g0, sacc[t1][1] - g1);
                apl[3] = packbf(sacc[t1][2] - g2, sacc[t1][3] - g3);
            }
            #pragma unroll
            for (int dp = 0; dp < 4; dp++) {
                uint32_t vh4[4], vl4[4];
                int r = jk * 16 + (sub & 1) * 8 + (lane & 7);
                int c = 2 * dp + (sub >> 1);
                uint32_t ad = kb0 + 16384 + swz(r, c);
                ldsm4t4(vh4, ad);
                ldsm4t4(vl4, ad + 8192);
                mma_bf16(oacc[2 * dp],     aph, vh4);
                mma_bf16(oacc[2 * dp + 1], aph, vh4 + 2);
                mma_bf16(oacc[2 * dp],     aph, vl4);
                mma_bf16(oacc[2 * dp + 1], aph, vl4 + 2);
                mma_bf16(oacc[2 * dp],     apl, vh4);
                mma_bf16(oacc[2 * dp + 1], apl, vh4 + 2);
            }
        }
        __syncthreads();
    }

    float ilo = 1.0f / l_lo, ihi = 1.0f / l_hi;
    size_t tau = (size_t)b * TT + g * GTT + 128 * qi + w * 16 + (lane >> 2);
    int colb = h * HSD + ((lane & 3) << 1);
    #pragma unroll
    for (int t = 0; t < 8; t++) {
        float v0 = oacc[t][0] * ilo, v1 = oacc[t][1] * ilo;
        float v2 = oacc[t][2] * ihi, v3 = oacc[t][3] * ihi;
        float h0 = hif(v0), h1 = hif(v1), h2 = hif(v2), h3 = hif(v3);
        size_t o0 = tau * CC + colb + t * 8;
        size_t o1 = (tau + 8) * CC + colb + t * 8;
        *(uint32_t*)(g_obh + o0) = packbf(h0, h1);
        *(uint32_t*)(g_obl + o0) = packbf(v0 - h0, v1 - h1);
        *(uint32_t*)(g_obh + o1) = packbf(h2, h3);
        *(uint32_t*)(g_obl + o1) = packbf(v2 - h2, v3 - h3);
    }
}

// =================== Pooling (qb/kb/vb; L=1 attention is identity) ===================
__global__ __launch_bounds__(64) void pool_k(
    const float* __restrict__ qp, const float* __restrict__ kp,
    const float* __restrict__ vp, float* __restrict__ out)
{
    int bx = blockIdx.x;
    int which = bx / 448;
    int rem = bx - which * 448;
    int g = rem % 7;
    int bh = rem / 7;
    size_t base = ((size_t)bh * GG + g) * GTT * HSD;
    const __nv_bfloat16* sh = (which == 0 ? g_qh : (which == 1 ? g_kh : g_vh)) + base;
    const __nv_bfloat16* sl = (which == 0 ? g_ql : (which == 1 ? g_kl : g_vl)) + base;
    const float* proj = (which == 0 ? qp : (which == 1 ? kp : vp));
    int hs = threadIdx.x;
    float acc = 0.f;
    #pragma unroll 8
    for (int t = 0; t < GTT; t++) {
        float v = __bfloat162float(sh[(size_t)t * HSD + hs])
                + __bfloat162float(sl[(size_t)t * HSD + hs]);
        acc = fmaf(v, proj[t], acc);
    }
    out[(size_t)BB * TT * CC + (size_t)which * (BB * HH * 7 * HSD)
        + (size_t)(bh * 7 + g) * HSD + hs] = acc;
}

// =================== launch ===================
extern "C" void kernel_launch(void* const* d_in, const int* in_sizes, int n_in,
                              void* d_out, int out_size) {
    (void)in_sizes; (void)n_in; (void)out_size;
    const float* x    = (const float*)d_in[0];
    const float* Wqkv = (const float*)d_in[1];
    const float* Wo   = (const float*)d_in[2];
    const float* qp   = (const float*)d_in[3];
    const float* kp   = (const float*)d_in[4];
    const float* vp   = (const float*)d_in[5];
    const float* fc   = (const float*)d_in[6];
    const float* fs   = (const float*)d_in[7];
    float* out = (float*)d_out;

    float* qkv_p;
    __nv_bfloat16 *xh, *xl, *wqh, *wql, *woh, *wol, *obh, *obl;
    cudaGetSymbolAddress((void**)&qkv_p, g_qkv);
    cudaGetSymbolAddress((void**)&xh, g_xh);
    cudaGetSymbolAddress((void**)&xl, g_xl);
    cudaGetSymbolAddress((void**)&wqh, g_wqh);
    cudaGetSymbolAddress((void**)&wql, g_wql);
    cudaGetSymbolAddress((void**)&woh, g_woh);
    cudaGetSymbolAddress((void**)&wol, g_wol);
    cudaGetSymbolAddress((void**)&obh, g_obh);
    cudaGetSymbolAddress((void**)&obl, g_obl);

    cudaFuncSetAttribute(attn_k, cudaFuncAttributeMaxDynamicSharedMemorySize,
                         ATT_SMEM);
    cudaFuncSetAttribute(gemm3_k, cudaFuncAttributeMaxDynamicSharedMemorySize,
                         GEMM_SMEM);

    // 0) split inputs to bf16 hi/lo
    int nx = BB * TT * CC;
    split_k<<<(nx / 4 + 255) / 256, 256>>>(x, xh, xl, nx);
    int nwq = CC * 3 * CC;
    split_k<<<(nwq / 4 + 255) / 256, 256>>>(Wqkv, wqh, wql, nwq);
    int nwo = CC * CC;
    split_k<<<(nwo / 4 + 255) / 256, 256>>>(Wo, woh, wol, nwo);

    // 1) qkv = x @ Wqkv  (tensor cores)
    dim3 g1(3 * CC / 128, BB * TT / 128);
    gemm3_k<<<g1, 256, GEMM_SMEM>>>(xh, xl, wqh, wql, qkv_p,
                                    BB * TT, 3 * CC, CC);
    // 2) rope + grouped scatter (split bf16)
    rope_k<<<(BB * HH * TT * 32) / 256, 256>>>(fc, fs);
    // 3) tensor-core block-causal attention (emits split-bf16 o)
    attn_k<<<BB * HH * GG * 4, 256, ATT_SMEM>>>();
    // 4) qb/kb/vb pools (tail of d_out)
    pool_k<<<3 * BB * HH * 7, 64>>>(qp, kp, vp, out);
    // 5) out = o @ Wo (head of d_out)
    dim3 g2(CC / 128, BB * TT / 128);
    gemm3_k<<<g2, 256, GEMM_SMEM>>>(obh, obl, woh, wol, out,
                                    BB * TT, CC, CC);
}

// round 9
// speedup vs baseline: 2.0905x; 1.3980x over previous
#include <cuda_runtime.h>
#include <cuda_fp16.h>
#include <cstdint>
#include <cstddef>

#define BB 4
#define TT 4096
#define CC 1024
#define HH 16
#define GG 8
#define HSD 64
#define GTT 512

// ---- scratch (static device globals; no runtime allocation allowed) ----
__device__ __align__(16) float g_qkv[(size_t)BB*TT*3*CC];        // 192 MB
// grouped, rope'd fp16 q/k/v  (q hi-only; k/v hi+lo)
__device__ __align__(16) __half g_qh[(size_t)BB*HH*GG*GTT*HSD];
__device__ __align__(16) __half g_kh[(size_t)BB*HH*GG*GTT*HSD];
__device__ __align__(16) __half g_kl[(size_t)BB*HH*GG*GTT*HSD];
__device__ __align__(16) __half g_vh[(size_t)BB*HH*GG*GTT*HSD];
__device__ __align__(16) __half g_vl[(size_t)BB*HH*GG*GTT*HSD];
// GEMM operands: left hi-only, right hi+lo
__device__ __align__(16) __half g_xh[(size_t)BB*TT*CC];
__device__ __align__(16) __half g_wqh[(size_t)CC*3*CC];
__device__ __align__(16) __half g_wql[(size_t)CC*3*CC];
__device__ __align__(16) __half g_woh[(size_t)CC*CC];
__device__ __align__(16) __half g_wol[(size_t)CC*CC];
__device__ __align__(16) __half g_obh[(size_t)BB*TT*CC];

// =================== small helpers ===================
__device__ __forceinline__ float hif16(float x) {
    return __half2float(__float2half(x));
}
__device__ __forceinline__ uint32_t packh(float lo, float hi) {
    uint32_t r;
    asm("cvt.rn.f16x2.f32 %0,%1,%2;" : "=r"(r) : "f"(hi), "f"(lo));
    return r;
}
__device__ __forceinline__ void cp16(void* s, const void* g) {
    uint32_t sa = (uint32_t)__cvta_generic_to_shared(s);
    asm volatile("cp.async.cg.shared.global [%0], [%1], 16;" :: "r"(sa), "l"(g));
}
__device__ __forceinline__ void cp16s(uint32_t sa, const void* g) {
    asm volatile("cp.async.cg.shared.global [%0], [%1], 16;" :: "r"(sa), "l"(g));
}
__device__ __forceinline__ void ldsm4(uint32_t* r, uint32_t a) {
    asm volatile("ldmatrix.sync.aligned.m8n8.x4.shared.b16 {%0,%1,%2,%3},[%4];"
        : "=r"(r[0]), "=r"(r[1]), "=r"(r[2]), "=r"(r[3]) : "r"(a));
}
__device__ __forceinline__ void ldsm4t(uint32_t* r0, uint32_t* r1, uint32_t a) {
    asm volatile("ldmatrix.sync.aligned.m8n8.x4.trans.shared.b16 {%0,%1,%2,%3},[%4];"
        : "=r"(r0[0]), "=r"(r0[1]), "=r"(r1[0]), "=r"(r1[1]) : "r"(a));
}
__device__ __forceinline__ void ldsm4t4(uint32_t* r, uint32_t a) {
    asm volatile("ldmatrix.sync.aligned.m8n8.x4.trans.shared.b16 {%0,%1,%2,%3},[%4];"
        : "=r"(r[0]), "=r"(r[1]), "=r"(r[2]), "=r"(r[3]) : "r"(a));
}
__device__ __forceinline__ void mma_f16(float* d, const uint32_t* a,
                                        const uint32_t* b) {
    asm volatile("mma.sync.aligned.m16n8k16.row.col.f32.f16.f16.f32 "
        "{%0,%1,%2,%3},{%4,%5,%6,%7},{%8,%9},{%0,%1,%2,%3};"
        : "+f"(d[0]), "+f"(d[1]), "+f"(d[2]), "+f"(d[3])
        : "r"(a[0]), "r"(a[1]), "r"(a[2]), "r"(a[3]), "r"(b[0]), "r"(b[1]));
}
__device__ __forceinline__ uint32_t swz(int r, int c) {
    return (uint32_t)(r * 128 + ((c ^ (r & 7)) << 4));
}
__device__ __forceinline__ void store_split2h(
    __half* hi, __half* lo, size_t idx, float2 v)
{
    float h0 = hif16(v.x), h1 = hif16(v.y);
    *(uint32_t*)(hi + idx) = packh(h0, h1);
    *(uint32_t*)(lo + idx) = packh(v.x - h0, v.y - h1);
}

// =================== fp32 -> fp16 hi+lo (weights) ===================
__global__ __launch_bounds__(256) void split_k(
    const float* __restrict__ in, __half* __restrict__ hi,
    __half* __restrict__ lo, int n)
{
    int i = (blockIdx.x * 256 + threadIdx.x) * 4;
    if (i >= n) return;
    float4 v = *(const float4*)(in + i);
    float h0 = hif16(v.x), h1 = hif16(v.y), h2 = hif16(v.z), h3 = hif16(v.w);
    *(uint32_t*)(hi + i)     = packh(h0, h1);
    *(uint32_t*)(hi + i + 2) = packh(h2, h3);
    *(uint32_t*)(lo + i)     = packh(v.x - h0, v.y - h1);
    *(uint32_t*)(lo + i + 2) = packh(v.z - h2, v.w - h3);
}

// =================== fp32 -> fp16 hi only (left operands) ===================
__global__ __launch_bounds__(256) void convh_k(
    const float* __restrict__ in, __half* __restrict__ hi, int n)
{
    int i = (blockIdx.x * 256 + threadIdx.x) * 4;
    if (i >= n) return;
    float4 v = *(const float4*)(in + i);
    *(uint32_t*)(hi + i)     = packh(v.x, v.y);
    *(uint32_t*)(hi + i + 2) = packh(v.z, v.w);
}

// =================== fp16-split 2-pass tensor-core GEMM ===================
// C = A * (Bh + Bl), A fp16 hi-only. 3-stage cp.async, one barrier per kt.
#define SA_PITCH 40
#define SB_PITCH 136
#define AH_OFF 0
#define BH_OFF 5120
#define BL_OFF 9472
#define STG_ELEMS 13824
#define GEMM_SMEM (3 * STG_ELEMS * 2)

__device__ __forceinline__ void prefetch_tiles(
    __half* smbuf, const __half* A,
    const __half* Bh, const __half* Bl,
    int bm, int bn, int N, int K, int k0, int buf, int tid)
{
    __half* sb = smbuf + buf * STG_ELEMS;
    #pragma unroll
    for (int it = 0; it < 6; it++) {
        int gi = tid + it * 256;
        if (gi < 512) {
            int r = gi >> 2, c = gi & 3;
            cp16(sb + AH_OFF + r * SA_PITCH + c * 8,
                 A + (size_t)(bm + r) * K + k0 + c * 8);
        } else if (gi < 1024) {
            int g = gi - 512;
            int r = g >> 4, c = g & 15;
            cp16(sb + BH_OFF + r * SB_PITCH + c * 8,
                 Bh + (size_t)(k0 + r) * N + bn + c * 8);
        } else {
            int g = gi - 1024;
            int r = g >> 4, c = g & 15;
            cp16(sb + BL_OFF + r * SB_PITCH + c * 8,
                 Bl + (size_t)(k0 + r) * N + bn + c * 8);
        }
    }
    asm volatile("cp.async.commit_group;" ::: "memory");
}

__global__ __launch_bounds__(256) void gemm2p_k(
    const __half* __restrict__ A,
    const __half* __restrict__ Bh, const __half* __restrict__ Bl,
    float* __restrict__ C, int M, int N, int K)
{
    extern __shared__ __half smbuf[];
    int tid = threadIdx.x, lane = tid & 31, warp = tid >> 5;
    int bm = blockIdx.y * 128, bn = blockIdx.x * 128;
    int wm = (warp >> 2) * 64, wn = (warp & 3) * 32;
    uint32_t smb = (uint32_t)__cvta_generic_to_shared(smbuf);
    float acc[4][4][4] = {};
    int NK = K >> 5;

    prefetch_tiles(smbuf, A, Bh, Bl, bm, bn, N, K, 0, 0, tid);
    if (NK > 1)
        prefetch_tiles(smbuf, A, Bh, Bl, bm, bn, N, K, 32, 1, tid);

    int scur = 0, snx2 = 2;
    for (int kt = 0; kt < NK; kt++) {
        if (kt + 1 < NK)
            asm volatile("cp.async.wait_group 1;" ::: "memory");
        else
            asm volatile("cp.async.wait_group 0;" ::: "memory");
        __syncthreads();
        if (kt + 2 < NK)
            prefetch_tiles(smbuf, A, Bh, Bl, bm, bn, N, K,
                           (kt + 2) << 5, snx2, tid);
        int sb = scur * STG_ELEMS;
        #pragma unroll
        for (int ks = 0; ks < 2; ks++) {
            uint32_t aH[4][4], bH[4][2], bL[4][2];
            int arow = lane & 15;
            int acb = ks * 32 + ((lane >> 4) << 4);
            #pragma unroll
            for (int mt = 0; mt < 4; mt++) {
                uint32_t ad = smb + (uint32_t)((sb + AH_OFF) * 2
                            + (wm + mt * 16 + arow) * (SA_PITCH * 2) + acb);
                ldsm4(aH[mt], ad);
            }
            int bk = ks * 16 + (lane & 15);
            int bcb = (wn + ((lane >> 4) << 3)) * 2;
            #pragma unroll
            for (int p = 0; p < 2; p++) {
                uint32_t bd = smb + (uint32_t)((sb + BH_OFF) * 2
                            + bk * (SB_PITCH * 2) + bcb + p * 32);
                ldsm4t(bH[2 * p], bH[2 * p + 1], bd);
                ldsm4t(bL[2 * p], bL[2 * p + 1], bd + (BL_OFF - BH_OFF) * 2);
            }
            #pragma unroll
            for (int pass = 0; pass < 2; pass++) {
                #pragma unroll
                for (int mt = 0; mt < 4; mt++)
                    #pragma unroll
                    for (int nt = 0; nt < 4; nt++)
                        mma_f16(acc[mt][nt], aH[mt],
                                pass ? bL[nt] : bH[nt]);
            }
        }
        scur = (scur == 2) ? 0 : scur + 1;
        snx2 = (snx2 == 2) ? 0 : snx2 + 1;
    }
    #pragma unroll
    for (int mt = 0; mt < 4; mt++) {
        #pragma unroll
        for (int nt = 0; nt < 4; nt++) {
            int r = bm + wm + mt * 16 + (lane >> 2);
            int c = bn + wn + nt * 8 + ((lane & 3) << 1);
            *(float2*)&C[(size_t)r * N + c] =
                make_float2(acc[mt][nt][0], acc[mt][nt][1]);
            *(float2*)&C[(size_t)(r + 8) * N + c] =
                make_float2(acc[mt][nt][2], acc[mt][nt][3]);
        }
    }
}

// =================== RoPE + grouped scatter (fp16; q hi-only) ===================
__global__ __launch_bounds__(256) void rope_k(
    const float* __restrict__ fcos, const float* __restrict__ fsin)
{
    unsigned id = blockIdx.x * 256u + threadIdx.x;
    int j = id & 31;
    int t = (id >> 5) & (TT - 1);
    int h = (id >> 17) & (HH - 1);
    int b = id >> 21;
    const float* row = g_qkv + (size_t)(b * TT + t) * (3 * CC);
    float2 qv = *(const float2*)(row + h * HSD + 2 * j);
    float2 kv = *(const float2*)(row + CC + h * HSD + 2 * j);
    float2 vv = *(const float2*)(row + 2 * CC + h * HSD + 2 * j);
    float c = fcos[t * 32 + j];
    float s = fsin[t * 32 + j];
    float2 qo = make_float2(qv.x * c - qv.y * s, qv.x * s + qv.y * c);
    float2 ko = make_float2(kv.x * c - kv.y * s, kv.x * s + kv.y * c);
    int h2 = t & 15;
    int gq = h >> 1;
    int gtq = ((h & 1) << 8) | (t >> 4);
    size_t qidx = (((size_t)((b * HH + h2) * GG + gq) * GTT + gtq) * HSD) + 2 * j;
    *(uint32_t*)(g_qh + qidx) = packh(qo.x, qo.y);
    store_split2h(g_kh, g_kl, qidx, ko);
    int gv = t >> 9, gtv = t & 511;
    size_t vidx = (((size_t)((b * HH + h) * GG + gv) * GTT + gtv) * HSD) + 2 * j;
    store_split2h(g_vh, g_vl, vidx, vv);
}

// =================== tensor-core block-causal flash attention ===================
#define ATT_SMEM 65536

__global__ __launch_bounds__(256) void attn_k() {
    extern __shared__ __align__(16) char smraw[];
    uint32_t smb = (uint32_t)__cvta_generic_to_shared(smraw);
    int tid = threadIdx.x, lane = tid & 31, w = tid >> 5;
    int bx = blockIdx.x;
    int qi = bx & 3;
    int g  = (bx >> 2) & 7;
    int h  = (bx >> 5) & 15;
    int b  = bx >> 9;
    size_t gb = ((size_t)((b * HH + h) * GG + g)) * GTT * HSD;
    const __half* Qhp = g_qh + gb + (size_t)(128 * qi) * HSD;
    const __half* arrp[4] = { g_kh + gb, g_kl + gb, g_vh + gb, g_vl + gb };

    // stage Q hi (128x64 fp16 = 16KB) into buffer-1 region
    #pragma unroll
    for (int it = 0; it < 4; it++) {
        int cid = tid + it * 256;
        int r = cid >> 3, c = cid & 7;
        cp16s(smb + 32768 + swz(r, c), Qhp + r * HSD + c * 8);
    }
    asm volatile("cp.async.commit_group;" ::: "memory");
    asm volatile("cp.async.wait_group 0;" ::: "memory");
    __syncthreads();

    uint32_t qhf[4][4];
    int rq = w * 16;
    int sub = lane >> 3;
    #pragma unroll
    for (int kk = 0; kk < 4; kk++) {
        int r = rq + (sub & 1) * 8 + (lane & 7);
        int c = 2 * kk + (sub >> 1);
        ldsm4(qhf[kk], smb + 32768 + swz(r, c));
    }
    __syncthreads();

    int ntiles = 2 * qi + 2;

    {
        #pragma unroll
        for (int it = 0; it < 8; it++) {
            int cid = tid + it * 256;
            int arr = cid >> 9;
            int rc = cid & 511;
            int r = rc >> 3, c = rc & 7;
            cp16s(smb + arr * 8192 + swz(r, c),
                  arrp[arr] + (size_t)r * HSD + c * 8);
        }
        asm volatile("cp.async.commit_group;" ::: "memory");
    }

    float oacc[8][4] = {};
    float m_lo = -1e30f, m_hi = -1e30f, l_lo = 0.f, l_hi = 0.f;

    for (int kt = 0; kt < ntiles; kt++) {
        if (kt + 1 < ntiles) {
            int buf = (kt + 1) & 1;
            #pragma unroll
            for (int it = 0; it < 8; it++) {
                int cid = tid + it * 256;
                int arr = cid >> 9;
                int rc = cid & 511;
                int r = rc >> 3, c = rc & 7;
                cp16s(smb + buf * 32768 + arr * 8192 + swz(r, c),
                      arrp[arr] + (size_t)((kt + 1) * 64 + r) * HSD + c * 8);
            }
            asm volatile("cp.async.commit_group;" ::: "memory");
            asm volatile("cp.async.wait_group 1;" ::: "memory");
        } else {
            asm volatile("cp.async.wait_group 0;" ::: "memory");
        }
        __syncthreads();
        uint32_t kb0 = smb + (kt & 1) * 32768;

        // ---- S = Q (Kh + Kl)^T : 2-pass ----
        float sacc[8][4] = {};
        #pragma unroll
        for (int kk = 0; kk < 4; kk++) {
            #pragma unroll
            for (int tp = 0; tp < 4; tp++) {
                uint32_t kh4[4], kl4[4];
                int r = tp * 16 + (sub >> 1) * 8 + (lane & 7);
                int c = 2 * kk + (sub & 1);
                uint32_t ad = kb0 + swz(r, c);
                ldsm4(kh4, ad);
                ldsm4(kl4, ad + 8192);
                mma_f16(sacc[2 * tp],     qhf[kk], kh4);
                mma_f16(sacc[2 * tp + 1], qhf[kk], kh4 + 2);
                mma_f16(sacc[2 * tp],     qhf[kk], kl4);
                mma_f16(sacc[2 * tp + 1], qhf[kk], kl4 + 2);
            }
        }

        int rowl = 128 * qi + w * 16 + (lane >> 2);
        bool nm = (kt * 64 + 63) > (128 * qi + w * 16);
        #pragma unroll
        for (int t = 0; t < 8; t++) {
            #pragma unroll
            for (int e = 0; e < 4; e++) {
                float s = sacc[t][e] * 0.125f;
                if (nm) {
                    int col = kt * 64 + t * 8 + ((lane & 3) << 1) + (e & 1);
                    int row = rowl + ((e & 2) ? 8 : 0);
                    if (col > row) s = -1e30f;
                }
                sacc[t][e] = s;
            }
        }

        float mlo = -1e30f, mhi = -1e30f;
        #pragma unroll
        for (int t = 0; t < 8; t++) {
            mlo = fmaxf(mlo, fmaxf(sacc[t][0], sacc[t][1]));
            mhi = fmaxf(mhi, fmaxf(sacc[t][2], sacc[t][3]));
        }
        mlo = fmaxf(mlo, __shfl_xor_sync(0xffffffffu, mlo, 1));
        mlo = fmaxf(mlo, __shfl_xor_sync(0xffffffffu, mlo, 2));
        mhi = fmaxf(mhi, __shfl_xor_sync(0xffffffffu, mhi, 1));
        mhi = fmaxf(mhi, __shfl_xor_sync(0xffffffffu, mhi, 2));
        float nmlo = fmaxf(m_lo, mlo), nmhi = fmaxf(m_hi, mhi);
        float clo = __expf(m_lo - nmlo), chi = __expf(m_hi - nmhi);
        m_lo = nmlo; m_hi = nmhi;
        float slo = 0.f, shi = 0.f;
        #pragma unroll
        for (int t = 0; t < 8; t++) {
            float p0 = __expf(sacc[t][0] - nmlo);
            float p1 = __expf(sacc[t][1] - nmlo);
            float p2 = __expf(sacc[t][2] - nmhi);
            float p3 = __expf(sacc[t][3] - nmhi);
            sacc[t][0] = p0; sacc[t][1] = p1; sacc[t][2] = p2; sacc[t][3] = p3;
            slo += p0 + p1; shi += p2 + p3;
        }
        slo += __shfl_xor_sync(0xffffffffu, slo, 1);
        slo += __shfl_xor_sync(0xffffffffu, slo, 2);
        shi += __shfl_xor_sync(0xffffffffu, shi, 1);
        shi += __shfl_xor_sync(0xffffffffu, shi, 2);
        l_lo = l_lo * clo + slo;
        l_hi = l_hi * chi + shi;
        #pragma unroll
        for (int t = 0; t < 8; t++) {
            oacc[t][0] *= clo; oacc[t][1] *= clo;
            oacc[t][2] *= chi; oacc[t][3] *= chi;
        }

        // ---- O += P (Vh + Vl) : 2-pass, P hi-only ----
        #pragma unroll
        for (int jk = 0; jk < 4; jk++) {
            uint32_t aph[4];
            {
                int t0 = 2 * jk, t1 = t0 + 1;
                aph[0] = packh(sacc[t0][0], sacc[t0][1]);
                aph[1] = packh(sacc[t0][2], sacc[t0][3]);
                aph[2] = packh(sacc[t1][0], sacc[t1][1]);
                aph[3] = packh(sacc[t1][2], sacc[t1][3]);
            }
            #pragma unroll
            for (int dp = 0; dp < 4; dp++) {
                uint32_t vh4[4], vl4[4];
                int r = jk * 16 + (sub & 1) * 8 + (lane & 7);
                int c = 2 * dp + (sub >> 1);
                uint32_t ad = kb0 + 16384 + swz(r, c);
                ldsm4t4(vh4, ad);
                ldsm4t4(vl4, ad + 8192);
                mma_f16(oacc[2 * dp],     aph, vh4);
                mma_f16(oacc[2 * dp + 1], aph, vh4 + 2);
                mma_f16(oacc[2 * dp],     aph, vl4);
                mma_f16(oacc[2 * dp + 1], aph, vl4 + 2);
            }
        }
        __syncthreads();
    }

    // epilogue: normalize, un-group, emit fp16 hi
    float ilo = 1.0f / l_lo, ihi = 1.0f / l_hi;
    size_t tau = (size_t)b * TT + g * GTT + 128 * qi + w * 16 + (lane >> 2);
    int colb = h * HSD + ((lane & 3) << 1);
    #pragma unroll
    for (int t = 0; t < 8; t++) {
        float v0 = oacc[t][0] * ilo, v1 = oacc[t][1] * ilo;
        float v2 = oacc[t][2] * ihi, v3 = oacc[t][3] * ihi;
        size_t o0 = tau * CC + colb + t * 8;
        size_t o1 = (tau + 8) * CC + colb + t * 8;
        *(uint32_t*)(g_obh + o0) = packh(v0, v1);
        *(uint32_t*)(g_obh + o1) = packh(v2, v3);
    }
}

// =================== Pooling (qb/kb/vb; L=1 attention is identity) ===================
__global__ __launch_bounds__(64) void pool_k(
    const float* __restrict__ qp, const float* __restrict__ kp,
    const float* __restrict__ vp, float* __restrict__ out)
{
    int bx = blockIdx.x;
    int which = bx / 448;
    int rem = bx - which * 448;
    int g = rem % 7;
    int bh = rem / 7;
    size_t base = ((size_t)bh * GG + g) * GTT * HSD;
    const __half* sh = (which == 0 ? g_qh : (which == 1 ? g_kh : g_vh)) + base;
    const __half* sl = (which == 1 ? g_kl : g_vl) + base;   // unused for q
    const float* proj = (which == 0 ? qp : (which == 1 ? kp : vp));
    int hs = threadIdx.x;
    float acc = 0.f;
    if (which == 0) {
        #pragma unroll 8
        for (int t = 0; t < GTT; t++)
            acc = fmaf(__half2float(sh[(size_t)t * HSD + hs]), proj[t], acc);
    } else {
        #pragma unroll 8
        for (int t = 0; t < GTT; t++) {
            float v = __half2float(sh[(size_t)t * HSD + hs])
                    + __half2float(sl[(size_t)t * HSD + hs]);
            acc = fmaf(v, proj[t], acc);
        }
    }
    out[(size_t)BB * TT * CC + (size_t)which * (BB * HH * 7 * HSD)
        + (size_t)(bh * 7 + g) * HSD + hs] = acc;
}

// =================== launch ===================
extern "C" void kernel_launch(void* const* d_in, const int* in_sizes, int n_in,
                              void* d_out, int out_size) {
    (void)in_sizes; (void)n_in; (void)out_size;
    const float* x    = (const float*)d_in[0];
    const float* Wqkv = (const float*)d_in[1];
    const float* Wo   = (const float*)d_in[2];
    const float* qp   = (const float*)d_in[3];
    const float* kp   = (const float*)d_in[4];
    const float* vp   = (const float*)d_in[5];
    const float* fc   = (const float*)d_in[6];
    const float* fs   = (const float*)d_in[7];
    float* out = (float*)d_out;

    float* qkv_p;
    __half *xh, *wqh, *wql, *woh, *wol, *obh;
    cudaGetSymbolAddress((void**)&qkv_p, g_qkv);
    cudaGetSymbolAddress((void**)&xh, g_xh);
    cudaGetSymbolAddress((void**)&wqh, g_wqh);
    cudaGetSymbolAddress((void**)&wql, g_wql);
    cudaGetSymbolAddress((void**)&woh, g_woh);
    cudaGetSymbolAddress((void**)&wol, g_wol);
    cudaGetSymbolAddress((void**)&obh, g_obh);

    cudaFuncSetAttribute(attn_k, cudaFuncAttributeMaxDynamicSharedMemorySize,
                         ATT_SMEM);
    cudaFuncSetAttribute(gemm2p_k, cudaFuncAttributeMaxDynamicSharedMemorySize,
                         GEMM_SMEM);

    // 0) convert inputs: x hi-only; weights hi+lo
    int nx = BB * TT * CC;
    convh_k<<<(nx / 4 + 255) / 256, 256>>>(x, xh, nx);
    int nwq = CC * 3 * CC;
    split_k<<<(nwq / 4 + 255) / 256, 256>>>(Wqkv, wqh, wql, nwq);
    int nwo = CC * CC;
    split_k<<<(nwo / 4 + 255) / 256, 256>>>(Wo, woh, wol, nwo);

    // 1) qkv = x @ Wqkv  (fp16 2-pass tensor cores)
    dim3 g1(3 * CC / 128, BB * TT / 128);
    gemm2p_k<<<g1, 256, GEMM_SMEM>>>(xh, wqh, wql, qkv_p, BB * TT, 3 * CC, CC);
    // 2) rope + grouped scatter (fp16)
    rope_k<<<(BB * HH * TT * 32) / 256, 256>>>(fc, fs);
    // 3) tensor-core block-causal attention (emits fp16 o)
    attn_k<<<BB * HH * GG * 4, 256, ATT_SMEM>>>();
    // 4) qb/kb/vb pools (tail of d_out)
    pool_k<<<3 * BB * HH * 7, 64>>>(qp, kp, vp, out);
    // 5) out = o @ Wo (head of d_out)
    dim3 g2(CC / 128, BB * TT / 128);
    gemm2p_k<<<g2, 256, GEMM_SMEM>>>(obh, woh, wol, out, BB * TT, CC, CC);
}